// round 3
// baseline (speedup 1.0000x reference)
#include <cuda_runtime.h>
#include <cuda_bf16.h>

// Problem dims
#define BSZ 2
#define SLEN 2048
#define HDIM 512
#define NDIM 64
#define TTOT 4096   // BSZ*SLEN

// ---------------- scratch (device globals; no allocation allowed) ----------
__device__ __align__(16) float g_Ainv[NDIM * NDIM];
__device__ __align__(16) float g_p[TTOT * NDIM];      // p = x @ B_w^T
__device__ __align__(16) float g_hs[TTOT * NDIM];     // scan states

__device__ __forceinline__ float fast_exp2(float x) {
    float y;
    asm("ex2.approx.ftz.f32 %0, %1;" : "=f"(y) : "f"(x));
    return y;
}

// ===========================================================================
// kernel_prep: Gauss-Jordan inverse of A (64x64) with partial pivoting,
// + one Newton refinement step. One block, 256 threads. Dynamic smem.
// layout: M[64][132] (augmented [A|I], later reloaded A), X[64][68], R[64][68]
// ===========================================================================
#define PREP_SMEM_FLOATS (64*132 + 64*68 + 64*68)

__global__ void kernel_prep(const float* __restrict__ A) {
    extern __shared__ float sm[];
    float* M = sm;                 // 64 x 132
    float* X = M + 64 * 132;       // 64 x 68
    float* R = X + 64 * 68;        // 64 x 68
    __shared__ int s_piv;
    __shared__ float s_scale;
    const int tid = threadIdx.x;

    // load [A | I]
    for (int e = tid; e < 64 * 64; e += 256) {
        int i = e >> 6, j = e & 63;
        M[i * 132 + j] = A[e];
        M[i * 132 + 64 + j] = (i == j) ? 1.0f : 0.0f;
    }
    __syncthreads();

    const int jcol = tid & 127;
    const int i0 = tid >> 7;   // 0 or 1

    for (int k = 0; k < 64; ++k) {
        // partial pivot: warp 0 argmax over |M[i][k]|, i >= k
        if (tid < 32) {
            float best = -1.0f; int bi = k;
            for (int i = k + tid; i < 64; i += 32) {
                float v = fabsf(M[i * 132 + k]);
                if (v > best) { best = v; bi = i; }
            }
            #pragma unroll
            for (int off = 16; off > 0; off >>= 1) {
                float ob = __shfl_xor_sync(0xffffffffu, best, off);
                int obi  = __shfl_xor_sync(0xffffffffu, bi, off);
                if (ob > best) { best = ob; bi = obi; }
            }
            if (tid == 0) s_piv = bi;
        }
        __syncthreads();
        const int piv = s_piv;
        if (tid < 128 && piv != k) {
            float a = M[k * 132 + jcol];
            float b = M[piv * 132 + jcol];
            M[k * 132 + jcol] = b;
            M[piv * 132 + jcol] = a;
        }
        __syncthreads();
        if (tid == 0) s_scale = 1.0f / M[k * 132 + k];
        __syncthreads();
        if (tid < 128) M[k * 132 + jcol] *= s_scale;
        __syncthreads();
        // eliminate (skip column k writes -> no race on M[i][k]; stale col never read)
        {
            const float fkj = M[k * 132 + jcol];
            if (jcol != k) {
                #pragma unroll 8
                for (int r = 0; r < 32; ++r) {
                    int i = i0 + 2 * r;
                    if (i != k) {
                        M[i * 132 + jcol] = fmaf(-M[i * 132 + k], fkj, M[i * 132 + jcol]);
                    }
                }
            }
        }
        __syncthreads();
    }

    // X = right half; reload A into left half
    for (int e = tid; e < 4096; e += 256) {
        int i = e >> 6, j = e & 63;
        X[i * 68 + j] = M[i * 132 + 64 + j];
    }
    __syncthreads();
    for (int e = tid; e < 4096; e += 256) {
        int i = e >> 6, j = e & 63;
        M[i * 132 + j] = A[e];
    }
    __syncthreads();

    // R = I - A*X
    for (int o = tid; o < 1024; o += 256) {
        int i = o >> 4, j4 = (o & 15) * 4;
        float4 acc;
        acc.x = (i == j4 + 0) ? 1.0f : 0.0f;
        acc.y = (i == j4 + 1) ? 1.0f : 0.0f;
        acc.z = (i == j4 + 2) ? 1.0f : 0.0f;
        acc.w = (i == j4 + 3) ? 1.0f : 0.0f;
        #pragma unroll 8
        for (int k2 = 0; k2 < 64; ++k2) {
            float a = M[i * 132 + k2];
            float4 xv = *(const float4*)&X[k2 * 68 + j4];
            acc.x = fmaf(-a, xv.x, acc.x);
            acc.y = fmaf(-a, xv.y, acc.y);
            acc.z = fmaf(-a, xv.z, acc.z);
            acc.w = fmaf(-a, xv.w, acc.w);
        }
        *(float4*)&R[i * 68 + j4] = acc;
    }
    __syncthreads();

    // Ainv = X + X*R
    for (int o = tid; o < 1024; o += 256) {
        int i = o >> 4, j4 = (o & 15) * 4;
        float4 acc = *(const float4*)&X[i * 68 + j4];
        #pragma unroll 8
        for (int k2 = 0; k2 < 64; ++k2) {
            float a = X[i * 68 + k2];
            float4 rv = *(const float4*)&R[k2 * 68 + j4];
            acc.x = fmaf(a, rv.x, acc.x);
            acc.y = fmaf(a, rv.y, acc.y);
            acc.z = fmaf(a, rv.z, acc.z);
            acc.w = fmaf(a, rv.w, acc.w);
        }
        *(float4*)&g_Ainv[i * 64 + j4] = acc;
    }
}

// ===========================================================================
// kernel_p: p = x @ B_w^T   (4096 x 64, K=512), NT GEMM.
// BM=32, BN=64, BK=32, 256 threads, 2x4 microtile, double-buffered.
// grid: 128 blocks (row blocks).
// ===========================================================================
__global__ void kernel_p(const float* __restrict__ Xin, const float* __restrict__ Bw) {
    __shared__ float As[2][32][36];
    __shared__ float Bs[2][32][68];
    const int tid = threadIdx.x;
    const int m0 = blockIdx.x * 32;
    const int tx = tid & 15, ty = tid >> 4;

    const int ar  = tid >> 3;          // 0..31
    const int akq = (tid & 7) * 4;     // 0..28
    const int br0 = ar;                // 0..31
    const int br1 = 32 + ar;           // 32..63

    float acc[2][4] = {};
    float4 pa, pb0, pb1;

    // preload tile 0
    {
        pa  = *(const float4*)(Xin + (m0 + ar) * 512 + akq);
        pb0 = *(const float4*)(Bw + br0 * 512 + akq);
        pb1 = *(const float4*)(Bw + br1 * 512 + akq);
    }
    {
        As[0][akq+0][ar] = pa.x;  As[0][akq+1][ar] = pa.y;
        As[0][akq+2][ar] = pa.z;  As[0][akq+3][ar] = pa.w;
        Bs[0][akq+0][br0] = pb0.x; Bs[0][akq+1][br0] = pb0.y;
        Bs[0][akq+2][br0] = pb0.z; Bs[0][akq+3][br0] = pb0.w;
        Bs[0][akq+0][br1] = pb1.x; Bs[0][akq+1][br1] = pb1.y;
        Bs[0][akq+2][br1] = pb1.z; Bs[0][akq+3][br1] = pb1.w;
    }
    __syncthreads();

    int buf = 0;
    for (int kt = 0; kt < 16; ++kt) {
        if (kt + 1 < 16) {
            int kk = (kt + 1) * 32;
            pa  = *(const float4*)(Xin + (m0 + ar) * 512 + kk + akq);
            pb0 = *(const float4*)(Bw + br0 * 512 + kk + akq);
            pb1 = *(const float4*)(Bw + br1 * 512 + kk + akq);
        }
        #pragma unroll
        for (int k = 0; k < 32; ++k) {
            float a0 = As[buf][k][ty * 2 + 0];
            float a1 = As[buf][k][ty * 2 + 1];
            float4 bv = *(const float4*)&Bs[buf][k][tx * 4];
            acc[0][0] = fmaf(a0, bv.x, acc[0][0]);
            acc[0][1] = fmaf(a0, bv.y, acc[0][1]);
            acc[0][2] = fmaf(a0, bv.z, acc[0][2]);
            acc[0][3] = fmaf(a0, bv.w, acc[0][3]);
            acc[1][0] = fmaf(a1, bv.x, acc[1][0]);
            acc[1][1] = fmaf(a1, bv.y, acc[1][1]);
            acc[1][2] = fmaf(a1, bv.z, acc[1][2]);
            acc[1][3] = fmaf(a1, bv.w, acc[1][3]);
        }
        if (kt + 1 < 16) {
            int nb = buf ^ 1;
            As[nb][akq+0][ar] = pa.x;  As[nb][akq+1][ar] = pa.y;
            As[nb][akq+2][ar] = pa.z;  As[nb][akq+3][ar] = pa.w;
            Bs[nb][akq+0][br0] = pb0.x; Bs[nb][akq+1][br0] = pb0.y;
            Bs[nb][akq+2][br0] = pb0.z; Bs[nb][akq+3][br0] = pb0.w;
            Bs[nb][akq+0][br1] = pb1.x; Bs[nb][akq+1][br1] = pb1.y;
            Bs[nb][akq+2][br1] = pb1.z; Bs[nb][akq+3][br1] = pb1.w;
            __syncthreads();
            buf = nb;
        }
    }

    // epilogue
    #pragma unroll
    for (int i = 0; i < 2; ++i) {
        float4 o;
        o.x = acc[i][0]; o.y = acc[i][1]; o.z = acc[i][2]; o.w = acc[i][3];
        *(float4*)&g_p[(m0 + ty * 2 + i) * 64 + tx * 4] = o;
    }
}

// ===========================================================================
// kernel_scan: chunked selective scan.
// 128 blocks (chunks of 32 timesteps + 8-step warmup), 256 threads.
// per step: A_bar = exp2(delta * A*log2e) ; h' = h@A_bar + A_bar@v - v
// dynamic smem: sA[64*65], sAbar[64*65] (first holds Ainv), sP[40*64],
//               sV[40*64], sDelta[64], sPart[256], sH[64]
// ===========================================================================
#define SCAN_SMEM_FLOATS (64*65 + 64*65 + 40*64 + 40*64 + 64 + 256 + 64)

__global__ void kernel_scan(const float* __restrict__ A, const float* __restrict__ dlt) {
    extern __shared__ float sm[];
    float* sA    = sm;                  // 64*65, A * log2(e)
    float* sAbar = sA + 64 * 65;        // 64*65 (Ainv during v phase)
    float* sP    = sAbar + 64 * 65;     // 40*64
    float* sV    = sP + 40 * 64;        // 40*64
    float* sDelta= sV + 40 * 64;        // 64
    float* sPart = sDelta + 64;         // 4*64
    float* sH    = sPart + 256;         // 64

    const int tid = threadIdx.x;
    const int g = blockIdx.x;
    const int lc = g & 63;
    const int warm = lc ? 8 : 0;
    const int t0g = g * 32 - warm;      // global start timestep
    const int nsteps = 32 + warm;

    const float LOG2E = 1.4426950408889634f;

    for (int e = tid; e < 4096; e += 256) {
        int i = e >> 6, j = e & 63;
        sA[i * 65 + j] = A[e] * LOG2E;
        sAbar[i * 65 + j] = g_Ainv[e];      // Ainv, consumed by v phase
    }
    for (int e = tid; e < nsteps * 64; e += 256) {
        sP[e] = g_p[t0g * 64 + e];
    }
    if (tid < nsteps) sDelta[tid] = dlt[t0g + tid];
    if (tid < 64) sH[tid] = 0.0f;
    __syncthreads();

    // v[t] = Ainv @ p[t]
    for (int o = tid; o < nsteps * 64; o += 256) {
        int t = o >> 6, m = o & 63;
        float acc = 0.0f;
        #pragma unroll 8
        for (int k = 0; k < 64; ++k) {
            acc = fmaf(sAbar[m * 65 + k], sP[t * 64 + k], acc);
        }
        sV[o] = acc;
    }
    __syncthreads();

    const int n = tid & 63, q = tid >> 6;
    const int mbase = q * 16;

    for (int j = 0; j < nsteps; ++j) {
        const float dj = sDelta[j];
        // phase A: A_bar = exp2(dj * sA)
        #pragma unroll
        for (int r = 0; r < 16; ++r) {
            int e = tid + 256 * r;
            int i = e >> 6, j2 = e & 63;
            sAbar[i * 65 + j2] = fast_exp2(dj * sA[i * 65 + j2]);
        }
        __syncthreads();
        // phase B: partials of h@A_bar + A_bar@v
        {
            const float* vj = &sV[j * 64];
            float acc = 0.0f;
            #pragma unroll
            for (int mi = 0; mi < 16; ++mi) {
                int m = mbase + mi;
                acc = fmaf(sH[m], sAbar[m * 65 + n], acc);
                acc = fmaf(sAbar[n * 65 + m], vj[m], acc);
            }
            sPart[q * 64 + n] = acc;
        }
        __syncthreads();
        // update h (threads 0..63)
        if (tid < 64) {
            float h = sPart[tid] + sPart[64 + tid] + sPart[128 + tid] + sPart[192 + tid]
                      - sV[j * 64 + tid];
            sH[tid] = h;
            if (j >= warm) g_hs[(t0g + j) * 64 + tid] = h;
        }
        // next phase A doesn't touch sH/sPart; its trailing sync orders the update.
    }
}

// ===========================================================================
// kernel_y: y = x @ D_w^T + hs @ C_w^T + (C_b + D_b)
// NT GEMM, M=4096, N=512, K=512 then K=64 (dual source).
// BM=BN=128, BK=16, 256 threads, 8x8 microtile, warp tile 32x64 (4x2 warps),
// double-buffered, single sync per k-tile. grid = (4 col, 32 row).
// ===========================================================================
__global__ void kernel_y(const float* __restrict__ Xin, const float* __restrict__ Dw,
                         const float* __restrict__ Cw,
                         const float* __restrict__ Cb, const float* __restrict__ Db,
                         float* __restrict__ Y) {
    __shared__ float As[2][16][132];
    __shared__ float Bs[2][16][132];
    const int tid = threadIdx.x;
    const int m0 = blockIdx.y * 128;
    const int n0 = blockIdx.x * 128;

    // loader indices: 2 float4 per operand per thread
    const int r0 = tid >> 2;               // 0..63
    const int r1 = 64 + r0;                // 64..127
    const int kq = (tid & 3) * 4;          // 0,4,8,12

    // warp-tile compute layout
    const int w = tid >> 5, lane = tid & 31;
    const int wm = w & 3, wn = w >> 2;     // 4 x 2 warps
    const int r = lane >> 3, c = lane & 7; // 4 x 8 threads
    const int aoff = wm * 32 + r * 8;
    const int boff0 = wn * 64 + c * 4;
    const int boff1 = boff0 + 32;

    float acc[8][8] = {};
    float4 pa0, pa1, pb0, pb1;

    // tile fetch: kt in [0,32) -> x/Dw K=512; kt in [32,36) -> hs/Cw K=64
    auto fetch = [&](int kt) {
        if (kt < 32) {
            int kk = kt * 16;
            pa0 = *(const float4*)(Xin + (m0 + r0) * 512 + kk + kq);
            pa1 = *(const float4*)(Xin + (m0 + r1) * 512 + kk + kq);
            pb0 = *(const float4*)(Dw + (n0 + r0) * 512 + kk + kq);
            pb1 = *(const float4*)(Dw + (n0 + r1) * 512 + kk + kq);
        } else {
            int kk = (kt - 32) * 16;
            pa0 = *(const float4*)(g_hs + (m0 + r0) * 64 + kk + kq);
            pa1 = *(const float4*)(g_hs + (m0 + r1) * 64 + kk + kq);
            pb0 = *(const float4*)(Cw + (n0 + r0) * 64 + kk + kq);
            pb1 = *(const float4*)(Cw + (n0 + r1) * 64 + kk + kq);
        }
    };
    auto stash = [&](int b) {
        As[b][kq+0][r0] = pa0.x; As[b][kq+1][r0] = pa0.y;
        As[b][kq+2][r0] = pa0.z; As[b][kq+3][r0] = pa0.w;
        As[b][kq+0][r1] = pa1.x; As[b][kq+1][r1] = pa1.y;
        As[b][kq+2][r1] = pa1.z; As[b][kq+3][r1] = pa1.w;
        Bs[b][kq+0][r0] = pb0.x; Bs[b][kq+1][r0] = pb0.y;
        Bs[b][kq+2][r0] = pb0.z; Bs[b][kq+3][r0] = pb0.w;
        Bs[b][kq+0][r1] = pb1.x; Bs[b][kq+1][r1] = pb1.y;
        Bs[b][kq+2][r1] = pb1.z; Bs[b][kq+3][r1] = pb1.w;
    };

    fetch(0);
    stash(0);
    __syncthreads();

    int buf = 0;
    for (int kt = 0; kt < 36; ++kt) {
        if (kt + 1 < 36) fetch(kt + 1);
        #pragma unroll
        for (int k = 0; k < 16; ++k) {
            float4 a0 = *(const float4*)&As[buf][k][aoff];
            float4 a1 = *(const float4*)&As[buf][k][aoff + 4];
            float4 b0 = *(const float4*)&Bs[buf][k][boff0];
            float4 b1 = *(const float4*)&Bs[buf][k][boff1];
            float av[8] = {a0.x, a0.y, a0.z, a0.w, a1.x, a1.y, a1.z, a1.w};
            float bv[8] = {b0.x, b0.y, b0.z, b0.w, b1.x, b1.y, b1.z, b1.w};
            #pragma unroll
            for (int i = 0; i < 8; ++i) {
                #pragma unroll
                for (int jj = 0; jj < 8; ++jj) {
                    acc[i][jj] = fmaf(av[i], bv[jj], acc[i][jj]);
                }
            }
        }
        if (kt + 1 < 36) {
            stash(buf ^ 1);
            __syncthreads();
            buf ^= 1;
        }
    }

    // epilogue with combined bias
    const int cg0 = n0 + boff0;
    const int cg1 = n0 + boff1;
    float4 cb0 = *(const float4*)(Cb + cg0);
    float4 db0 = *(const float4*)(Db + cg0);
    float4 cb1 = *(const float4*)(Cb + cg1);
    float4 db1 = *(const float4*)(Db + cg1);
    float4 bia0 = {cb0.x + db0.x, cb0.y + db0.y, cb0.z + db0.z, cb0.w + db0.w};
    float4 bia1 = {cb1.x + db1.x, cb1.y + db1.y, cb1.z + db1.z, cb1.w + db1.w};

    #pragma unroll
    for (int i = 0; i < 8; ++i) {
        int gm = m0 + aoff + i;
        float4 o0 = {acc[i][0] + bia0.x, acc[i][1] + bia0.y,
                     acc[i][2] + bia0.z, acc[i][3] + bia0.w};
        float4 o1 = {acc[i][4] + bia1.x, acc[i][5] + bia1.y,
                     acc[i][6] + bia1.z, acc[i][7] + bia1.w};
        *(float4*)(Y + gm * 512 + cg0) = o0;
        *(float4*)(Y + gm * 512 + cg1) = o1;
    }
}

// ===========================================================================
extern "C" void kernel_launch(void* const* d_in, const int* in_sizes, int n_in,
                              void* d_out, int out_size) {
    const float* x   = (const float*)d_in[0];   // (B,S,H)
    const float* dlt = (const float*)d_in[1];   // (B,S)
    const float* A   = (const float*)d_in[2];   // (N,N)
    const float* Bw  = (const float*)d_in[3];   // (N,H)
    const float* Cw  = (const float*)d_in[4];   // (H,N)
    const float* Cb  = (const float*)d_in[5];   // (H)
    const float* Dw  = (const float*)d_in[6];   // (H,H)
    const float* Db  = (const float*)d_in[7];   // (H)
    float* Y = (float*)d_out;

    const int prep_smem = PREP_SMEM_FLOATS * 4;
    const int scan_smem = SCAN_SMEM_FLOATS * 4;
    cudaFuncSetAttribute(kernel_prep, cudaFuncAttributeMaxDynamicSharedMemorySize, prep_smem);
    cudaFuncSetAttribute(kernel_scan, cudaFuncAttributeMaxDynamicSharedMemorySize, scan_smem);

    kernel_p<<<128, 256>>>(x, Bw);
    kernel_prep<<<1, 256, prep_smem>>>(A);
    kernel_scan<<<128, 256, scan_smem>>>(A, dlt);
    kernel_y<<<dim3(4, 32), 256>>>(x, Dw, Cw, Cb, Db, Y);
}

// round 4
// speedup vs baseline: 1.1455x; 1.1455x over previous
#include <cuda_runtime.h>
#include <cuda_bf16.h>

// Problem dims
#define BSZ 2
#define SLEN 2048
#define HDIM 512
#define NDIM 64
#define TTOT 4096   // BSZ*SLEN

// ---------------- scratch (device globals; no allocation allowed) ----------
__device__ __align__(16) float g_Ainv[NDIM * NDIM];
__device__ __align__(16) float g_p[TTOT * NDIM];      // p = x @ B_w^T
__device__ __align__(16) float g_hs[TTOT * NDIM];     // scan states

__device__ __forceinline__ float fast_exp2(float x) {
    float y;
    asm("ex2.approx.ftz.f32 %0, %1;" : "=f"(y) : "f"(x));
    return y;
}

// ===========================================================================
// kernel_prep: Gauss-Jordan inverse of A (64x64) with partial pivoting,
// + one Newton refinement step. One block, 256 threads. Dynamic smem.
// ===========================================================================
#define PREP_SMEM_FLOATS (64*132 + 64*68 + 64*68)

__global__ void kernel_prep(const float* __restrict__ A) {
    extern __shared__ float sm[];
    float* M = sm;                 // 64 x 132
    float* X = M + 64 * 132;       // 64 x 68
    float* R = X + 64 * 68;        // 64 x 68
    __shared__ int s_piv;
    __shared__ float s_scale;
    const int tid = threadIdx.x;

    // load [A | I]
    for (int e = tid; e < 64 * 64; e += 256) {
        int i = e >> 6, j = e & 63;
        M[i * 132 + j] = A[e];
        M[i * 132 + 64 + j] = (i == j) ? 1.0f : 0.0f;
    }
    __syncthreads();

    const int jcol = tid & 127;
    const int i0 = tid >> 7;   // 0 or 1

    for (int k = 0; k < 64; ++k) {
        if (tid < 32) {
            float best = -1.0f; int bi = k;
            for (int i = k + tid; i < 64; i += 32) {
                float v = fabsf(M[i * 132 + k]);
                if (v > best) { best = v; bi = i; }
            }
            #pragma unroll
            for (int off = 16; off > 0; off >>= 1) {
                float ob = __shfl_xor_sync(0xffffffffu, best, off);
                int obi  = __shfl_xor_sync(0xffffffffu, bi, off);
                if (ob > best) { best = ob; bi = obi; }
            }
            if (tid == 0) s_piv = bi;
        }
        __syncthreads();
        const int piv = s_piv;
        if (tid < 128 && piv != k) {
            float a = M[k * 132 + jcol];
            float b = M[piv * 132 + jcol];
            M[k * 132 + jcol] = b;
            M[piv * 132 + jcol] = a;
        }
        __syncthreads();
        if (tid == 0) s_scale = 1.0f / M[k * 132 + k];
        __syncthreads();
        if (tid < 128) M[k * 132 + jcol] *= s_scale;
        __syncthreads();
        {
            const float fkj = M[k * 132 + jcol];
            if (jcol != k) {
                #pragma unroll 8
                for (int r = 0; r < 32; ++r) {
                    int i = i0 + 2 * r;
                    if (i != k) {
                        M[i * 132 + jcol] = fmaf(-M[i * 132 + k], fkj, M[i * 132 + jcol]);
                    }
                }
            }
        }
        __syncthreads();
    }

    for (int e = tid; e < 4096; e += 256) {
        int i = e >> 6, j = e & 63;
        X[i * 68 + j] = M[i * 132 + 64 + j];
    }
    __syncthreads();
    for (int e = tid; e < 4096; e += 256) {
        int i = e >> 6, j = e & 63;
        M[i * 132 + j] = A[e];
    }
    __syncthreads();

    // R = I - A*X
    for (int o = tid; o < 1024; o += 256) {
        int i = o >> 4, j4 = (o & 15) * 4;
        float4 acc;
        acc.x = (i == j4 + 0) ? 1.0f : 0.0f;
        acc.y = (i == j4 + 1) ? 1.0f : 0.0f;
        acc.z = (i == j4 + 2) ? 1.0f : 0.0f;
        acc.w = (i == j4 + 3) ? 1.0f : 0.0f;
        #pragma unroll 8
        for (int k2 = 0; k2 < 64; ++k2) {
            float a = M[i * 132 + k2];
            float4 xv = *(const float4*)&X[k2 * 68 + j4];
            acc.x = fmaf(-a, xv.x, acc.x);
            acc.y = fmaf(-a, xv.y, acc.y);
            acc.z = fmaf(-a, xv.z, acc.z);
            acc.w = fmaf(-a, xv.w, acc.w);
        }
        *(float4*)&R[i * 68 + j4] = acc;
    }
    __syncthreads();

    // Ainv = X + X*R
    for (int o = tid; o < 1024; o += 256) {
        int i = o >> 4, j4 = (o & 15) * 4;
        float4 acc = *(const float4*)&X[i * 68 + j4];
        #pragma unroll 8
        for (int k2 = 0; k2 < 64; ++k2) {
            float a = X[i * 68 + k2];
            float4 rv = *(const float4*)&R[k2 * 68 + j4];
            acc.x = fmaf(a, rv.x, acc.x);
            acc.y = fmaf(a, rv.y, acc.y);
            acc.z = fmaf(a, rv.z, acc.z);
            acc.w = fmaf(a, rv.w, acc.w);
        }
        *(float4*)&g_Ainv[i * 64 + j4] = acc;
    }
}

// ===========================================================================
// kernel_p: p = x @ B_w^T   (4096 x 64, K=512), NT GEMM.
// ===========================================================================
__global__ void kernel_p(const float* __restrict__ Xin, const float* __restrict__ Bw) {
    __shared__ float As[2][32][36];
    __shared__ float Bs[2][32][68];
    const int tid = threadIdx.x;
    const int m0 = blockIdx.x * 32;
    const int tx = tid & 15, ty = tid >> 4;

    const int ar  = tid >> 3;
    const int akq = (tid & 7) * 4;
    const int br0 = ar;
    const int br1 = 32 + ar;

    float acc[2][4] = {};
    float4 pa, pb0, pb1;

    pa  = *(const float4*)(Xin + (m0 + ar) * 512 + akq);
    pb0 = *(const float4*)(Bw + br0 * 512 + akq);
    pb1 = *(const float4*)(Bw + br1 * 512 + akq);
    As[0][akq+0][ar] = pa.x;  As[0][akq+1][ar] = pa.y;
    As[0][akq+2][ar] = pa.z;  As[0][akq+3][ar] = pa.w;
    Bs[0][akq+0][br0] = pb0.x; Bs[0][akq+1][br0] = pb0.y;
    Bs[0][akq+2][br0] = pb0.z; Bs[0][akq+3][br0] = pb0.w;
    Bs[0][akq+0][br1] = pb1.x; Bs[0][akq+1][br1] = pb1.y;
    Bs[0][akq+2][br1] = pb1.z; Bs[0][akq+3][br1] = pb1.w;
    __syncthreads();

    int buf = 0;
    for (int kt = 0; kt < 16; ++kt) {
        if (kt + 1 < 16) {
            int kk = (kt + 1) * 32;
            pa  = *(const float4*)(Xin + (m0 + ar) * 512 + kk + akq);
            pb0 = *(const float4*)(Bw + br0 * 512 + kk + akq);
            pb1 = *(const float4*)(Bw + br1 * 512 + kk + akq);
        }
        #pragma unroll
        for (int k = 0; k < 32; ++k) {
            float a0 = As[buf][k][ty * 2 + 0];
            float a1 = As[buf][k][ty * 2 + 1];
            float4 bv = *(const float4*)&Bs[buf][k][tx * 4];
            acc[0][0] = fmaf(a0, bv.x, acc[0][0]);
            acc[0][1] = fmaf(a0, bv.y, acc[0][1]);
            acc[0][2] = fmaf(a0, bv.z, acc[0][2]);
            acc[0][3] = fmaf(a0, bv.w, acc[0][3]);
            acc[1][0] = fmaf(a1, bv.x, acc[1][0]);
            acc[1][1] = fmaf(a1, bv.y, acc[1][1]);
            acc[1][2] = fmaf(a1, bv.z, acc[1][2]);
            acc[1][3] = fmaf(a1, bv.w, acc[1][3]);
        }
        if (kt + 1 < 16) {
            int nb = buf ^ 1;
            As[nb][akq+0][ar] = pa.x;  As[nb][akq+1][ar] = pa.y;
            As[nb][akq+2][ar] = pa.z;  As[nb][akq+3][ar] = pa.w;
            Bs[nb][akq+0][br0] = pb0.x; Bs[nb][akq+1][br0] = pb0.y;
            Bs[nb][akq+2][br0] = pb0.z; Bs[nb][akq+3][br0] = pb0.w;
            Bs[nb][akq+0][br1] = pb1.x; Bs[nb][akq+1][br1] = pb1.y;
            Bs[nb][akq+2][br1] = pb1.z; Bs[nb][akq+3][br1] = pb1.w;
            __syncthreads();
            buf = nb;
        }
    }

    #pragma unroll
    for (int i = 0; i < 2; ++i) {
        float4 o;
        o.x = acc[i][0]; o.y = acc[i][1]; o.z = acc[i][2]; o.w = acc[i][3];
        *(float4*)&g_p[(m0 + ty * 2 + i) * 64 + tx * 4] = o;
    }
}

// ===========================================================================
// kernel_scan: chunked selective scan, 128 blocks (32 steps + 8 warmup).
// ===========================================================================
#define SCAN_SMEM_FLOATS (64*65 + 64*65 + 40*64 + 40*64 + 64 + 256 + 64)

__global__ void kernel_scan(const float* __restrict__ A, const float* __restrict__ dlt) {
    extern __shared__ float sm[];
    float* sA    = sm;
    float* sAbar = sA + 64 * 65;
    float* sP    = sAbar + 64 * 65;
    float* sV    = sP + 40 * 64;
    float* sDelta= sV + 40 * 64;
    float* sPart = sDelta + 64;
    float* sH    = sPart + 256;

    const int tid = threadIdx.x;
    const int g = blockIdx.x;
    const int lc = g & 63;
    const int warm = lc ? 8 : 0;
    const int t0g = g * 32 - warm;
    const int nsteps = 32 + warm;

    const float LOG2E = 1.4426950408889634f;

    for (int e = tid; e < 4096; e += 256) {
        int i = e >> 6, j = e & 63;
        sA[i * 65 + j] = A[e] * LOG2E;
        sAbar[i * 65 + j] = g_Ainv[e];
    }
    for (int e = tid; e < nsteps * 64; e += 256) {
        sP[e] = g_p[t0g * 64 + e];
    }
    if (tid < nsteps) sDelta[tid] = dlt[t0g + tid];
    if (tid < 64) sH[tid] = 0.0f;
    __syncthreads();

    // v[t] = Ainv @ p[t]
    for (int o = tid; o < nsteps * 64; o += 256) {
        int t = o >> 6, m = o & 63;
        float acc = 0.0f;
        #pragma unroll 8
        for (int k = 0; k < 64; ++k) {
            acc = fmaf(sAbar[m * 65 + k], sP[t * 64 + k], acc);
        }
        sV[o] = acc;
    }
    __syncthreads();

    const int n = tid & 63, q = tid >> 6;
    const int mbase = q * 16;

    for (int j = 0; j < nsteps; ++j) {
        const float dj = sDelta[j];
        #pragma unroll
        for (int r = 0; r < 16; ++r) {
            int e = tid + 256 * r;
            int i = e >> 6, j2 = e & 63;
            sAbar[i * 65 + j2] = fast_exp2(dj * sA[i * 65 + j2]);
        }
        __syncthreads();
        {
            const float* vj = &sV[j * 64];
            float acc = 0.0f;
            #pragma unroll
            for (int mi = 0; mi < 16; ++mi) {
                int m = mbase + mi;
                acc = fmaf(sH[m], sAbar[m * 65 + n], acc);
                acc = fmaf(sAbar[n * 65 + m], vj[m], acc);
            }
            sPart[q * 64 + n] = acc;
        }
        __syncthreads();
        if (tid < 64) {
            float h = sPart[tid] + sPart[64 + tid] + sPart[128 + tid] + sPart[192 + tid]
                      - sV[j * 64 + tid];
            sH[tid] = h;
            if (j >= warm) g_hs[(t0g + j) * 64 + tid] = h;
        }
        // next iteration's trailing __syncthreads (after the exp phase, which
        // touches neither sH nor sPart) orders this update before phase B.
    }
}

// ===========================================================================
// kernel_y1: Y = x @ D_w^T + (C_b + D_b).  M=4096, N=512, K=512.
// BM=BN=128, BK=16, 256 threads, 8x8 microtile, double buffered.
// ===========================================================================
__global__ void kernel_y1(const float* __restrict__ Xin, const float* __restrict__ Dw,
                          const float* __restrict__ Cb, const float* __restrict__ Db,
                          float* __restrict__ Y) {
    __shared__ float As[2][16][132];
    __shared__ float Bs[2][16][132];
    const int tid = threadIdx.x;
    const int m0 = blockIdx.y * 128;
    const int n0 = blockIdx.x * 128;

    const int r0 = tid >> 2;
    const int r1 = 64 + r0;
    const int kq = (tid & 3) * 4;

    const int w = tid >> 5, lane = tid & 31;
    const int wm = w & 3, wn = w >> 2;
    const int r = lane >> 3, c = lane & 7;
    const int aoff = wm * 32 + r * 8;
    const int boff0 = wn * 64 + c * 4;
    const int boff1 = boff0 + 32;

    float acc[8][8] = {};
    float4 pa0, pa1, pb0, pb1;

    auto fetch = [&](int kt) {
        int kk = kt * 16;
        pa0 = *(const float4*)(Xin + (m0 + r0) * 512 + kk + kq);
        pa1 = *(const float4*)(Xin + (m0 + r1) * 512 + kk + kq);
        pb0 = *(const float4*)(Dw + (n0 + r0) * 512 + kk + kq);
        pb1 = *(const float4*)(Dw + (n0 + r1) * 512 + kk + kq);
    };
    auto stash = [&](int b) {
        As[b][kq+0][r0] = pa0.x; As[b][kq+1][r0] = pa0.y;
        As[b][kq+2][r0] = pa0.z; As[b][kq+3][r0] = pa0.w;
        As[b][kq+0][r1] = pa1.x; As[b][kq+1][r1] = pa1.y;
        As[b][kq+2][r1] = pa1.z; As[b][kq+3][r1] = pa1.w;
        Bs[b][kq+0][r0] = pb0.x; Bs[b][kq+1][r0] = pb0.y;
        Bs[b][kq+2][r0] = pb0.z; Bs[b][kq+3][r0] = pb0.w;
        Bs[b][kq+0][r1] = pb1.x; Bs[b][kq+1][r1] = pb1.y;
        Bs[b][kq+2][r1] = pb1.z; Bs[b][kq+3][r1] = pb1.w;
    };

    fetch(0);
    stash(0);
    __syncthreads();

    int buf = 0;
    for (int kt = 0; kt < 32; ++kt) {
        if (kt + 1 < 32) fetch(kt + 1);
        #pragma unroll
        for (int k = 0; k < 16; ++k) {
            float4 a0 = *(const float4*)&As[buf][k][aoff];
            float4 a1 = *(const float4*)&As[buf][k][aoff + 4];
            float4 b0 = *(const float4*)&Bs[buf][k][boff0];
            float4 b1 = *(const float4*)&Bs[buf][k][boff1];
            float av[8] = {a0.x, a0.y, a0.z, a0.w, a1.x, a1.y, a1.z, a1.w};
            float bv[8] = {b0.x, b0.y, b0.z, b0.w, b1.x, b1.y, b1.z, b1.w};
            #pragma unroll
            for (int i = 0; i < 8; ++i) {
                #pragma unroll
                for (int jj = 0; jj < 8; ++jj) {
                    acc[i][jj] = fmaf(av[i], bv[jj], acc[i][jj]);
                }
            }
        }
        if (kt + 1 < 32) {
            stash(buf ^ 1);
            __syncthreads();
            buf ^= 1;
        }
    }

    const int cg0 = n0 + boff0;
    const int cg1 = n0 + boff1;
    float4 cb0 = *(const float4*)(Cb + cg0);
    float4 db0 = *(const float4*)(Db + cg0);
    float4 cb1 = *(const float4*)(Cb + cg1);
    float4 db1 = *(const float4*)(Db + cg1);
    float4 bia0 = {cb0.x + db0.x, cb0.y + db0.y, cb0.z + db0.z, cb0.w + db0.w};
    float4 bia1 = {cb1.x + db1.x, cb1.y + db1.y, cb1.z + db1.z, cb1.w + db1.w};

    #pragma unroll
    for (int i = 0; i < 8; ++i) {
        int gm = m0 + aoff + i;
        float4 o0 = {acc[i][0] + bia0.x, acc[i][1] + bia0.y,
                     acc[i][2] + bia0.z, acc[i][3] + bia0.w};
        float4 o1 = {acc[i][4] + bia1.x, acc[i][5] + bia1.y,
                     acc[i][6] + bia1.z, acc[i][7] + bia1.w};
        *(float4*)(Y + gm * 512 + cg0) = o0;
        *(float4*)(Y + gm * 512 + cg1) = o1;
    }
}

// ===========================================================================
// kernel_y2: Y += hs @ C_w^T.  M=4096, N=512, K=64.  Read-modify-write.
// ===========================================================================
__global__ void kernel_y2(const float* __restrict__ Cw, float* __restrict__ Y) {
    __shared__ float As[2][16][132];
    __shared__ float Bs[2][16][132];
    const int tid = threadIdx.x;
    const int m0 = blockIdx.y * 128;
    const int n0 = blockIdx.x * 128;

    const int r0 = tid >> 2;
    const int r1 = 64 + r0;
    const int kq = (tid & 3) * 4;

    const int w = tid >> 5, lane = tid & 31;
    const int wm = w & 3, wn = w >> 2;
    const int r = lane >> 3, c = lane & 7;
    const int aoff = wm * 32 + r * 8;
    const int boff0 = wn * 64 + c * 4;
    const int boff1 = boff0 + 32;

    float acc[8][8] = {};
    float4 pa0, pa1, pb0, pb1;

    auto fetch = [&](int kt) {
        int kk = kt * 16;
        pa0 = *(const float4*)(g_hs + (m0 + r0) * 64 + kk + kq);
        pa1 = *(const float4*)(g_hs + (m0 + r1) * 64 + kk + kq);
        pb0 = *(const float4*)(Cw + (n0 + r0) * 64 + kk + kq);
        pb1 = *(const float4*)(Cw + (n0 + r1) * 64 + kk + kq);
    };
    auto stash = [&](int b) {
        As[b][kq+0][r0] = pa0.x; As[b][kq+1][r0] = pa0.y;
        As[b][kq+2][r0] = pa0.z; As[b][kq+3][r0] = pa0.w;
        As[b][kq+0][r1] = pa1.x; As[b][kq+1][r1] = pa1.y;
        As[b][kq+2][r1] = pa1.z; As[b][kq+3][r1] = pa1.w;
        Bs[b][kq+0][r0] = pb0.x; Bs[b][kq+1][r0] = pb0.y;
        Bs[b][kq+2][r0] = pb0.z; Bs[b][kq+3][r0] = pb0.w;
        Bs[b][kq+0][r1] = pb1.x; Bs[b][kq+1][r1] = pb1.y;
        Bs[b][kq+2][r1] = pb1.z; Bs[b][kq+3][r1] = pb1.w;
    };

    fetch(0);
    stash(0);
    __syncthreads();

    int buf = 0;
    for (int kt = 0; kt < 4; ++kt) {
        if (kt + 1 < 4) fetch(kt + 1);
        #pragma unroll
        for (int k = 0; k < 16; ++k) {
            float4 a0 = *(const float4*)&As[buf][k][aoff];
            float4 a1 = *(const float4*)&As[buf][k][aoff + 4];
            float4 b0 = *(const float4*)&Bs[buf][k][boff0];
            float4 b1 = *(const float4*)&Bs[buf][k][boff1];
            float av[8] = {a0.x, a0.y, a0.z, a0.w, a1.x, a1.y, a1.z, a1.w};
            float bv[8] = {b0.x, b0.y, b0.z, b0.w, b1.x, b1.y, b1.z, b1.w};
            #pragma unroll
            for (int i = 0; i < 8; ++i) {
                #pragma unroll
                for (int jj = 0; jj < 8; ++jj) {
                    acc[i][jj] = fmaf(av[i], bv[jj], acc[i][jj]);
                }
            }
        }
        if (kt + 1 < 4) {
            stash(buf ^ 1);
            __syncthreads();
            buf ^= 1;
        }
    }

    const int cg0 = n0 + boff0;
    const int cg1 = n0 + boff1;
    #pragma unroll
    for (int i = 0; i < 8; ++i) {
        int gm = m0 + aoff + i;
        float4 y0 = *(const float4*)(Y + gm * 512 + cg0);
        float4 y1 = *(const float4*)(Y + gm * 512 + cg1);
        y0.x += acc[i][0]; y0.y += acc[i][1]; y0.z += acc[i][2]; y0.w += acc[i][3];
        y1.x += acc[i][4]; y1.y += acc[i][5]; y1.z += acc[i][6]; y1.w += acc[i][7];
        *(float4*)(Y + gm * 512 + cg0) = y0;
        *(float4*)(Y + gm * 512 + cg1) = y1;
    }
}

// ===========================================================================
// Stream/event context: created once on the first (correctness) call, which
// happens before graph capture. Launch topology is identical on every call.
// ===========================================================================
struct LaunchCtx {
    cudaStream_t s1, s2;
    cudaEvent_t e_root, e_prep, e_y1;
    LaunchCtx() {
        cudaStreamCreateWithFlags(&s1, cudaStreamNonBlocking);
        cudaStreamCreateWithFlags(&s2, cudaStreamNonBlocking);
        cudaEventCreateWithFlags(&e_root, cudaEventDisableTiming);
        cudaEventCreateWithFlags(&e_prep, cudaEventDisableTiming);
        cudaEventCreateWithFlags(&e_y1, cudaEventDisableTiming);
    }
};

extern "C" void kernel_launch(void* const* d_in, const int* in_sizes, int n_in,
                              void* d_out, int out_size) {
    const float* x   = (const float*)d_in[0];   // (B,S,H)
    const float* dlt = (const float*)d_in[1];   // (B,S)
    const float* A   = (const float*)d_in[2];   // (N,N)
    const float* Bw  = (const float*)d_in[3];   // (N,H)
    const float* Cw  = (const float*)d_in[4];   // (H,N)
    const float* Cb  = (const float*)d_in[5];   // (H)
    const float* Dw  = (const float*)d_in[6];   // (H,H)
    const float* Db  = (const float*)d_in[7];   // (H)
    float* Y = (float*)d_out;

    static LaunchCtx ctx;   // built on correctness call (pre-capture)

    const int prep_smem = PREP_SMEM_FLOATS * 4;
    const int scan_smem = SCAN_SMEM_FLOATS * 4;
    cudaFuncSetAttribute(kernel_prep, cudaFuncAttributeMaxDynamicSharedMemorySize, prep_smem);
    cudaFuncSetAttribute(kernel_scan, cudaFuncAttributeMaxDynamicSharedMemorySize, scan_smem);

    // Fork: s1 (prep), s2 (y1) branch off the main stream.
    cudaEventRecord(ctx.e_root, 0);
    cudaStreamWaitEvent(ctx.s1, ctx.e_root, 0);
    cudaStreamWaitEvent(ctx.s2, ctx.e_root, 0);

    kernel_prep<<<1, 256, prep_smem, ctx.s1>>>(A);
    cudaEventRecord(ctx.e_prep, ctx.s1);

    kernel_y1<<<dim3(4, 32), 256, 0, ctx.s2>>>(x, Dw, Cb, Db, Y);
    cudaEventRecord(ctx.e_y1, ctx.s2);

    kernel_p<<<128, 256>>>(x, Bw);                 // main stream
    cudaStreamWaitEvent(0, ctx.e_prep, 0);         // scan needs Ainv + p
    kernel_scan<<<128, 256, scan_smem>>>(A, dlt);
    cudaStreamWaitEvent(0, ctx.e_y1, 0);           // y2 accumulates into Y
    kernel_y2<<<dim3(4, 32), 256>>>(Cw, Y);
}

// round 5
// speedup vs baseline: 1.4575x; 1.2723x over previous
#include <cuda_runtime.h>
#include <cuda_bf16.h>

// Problem dims
#define BSZ 2
#define SLEN 2048
#define HDIM 512
#define NDIM 64
#define TTOT 4096   // BSZ*SLEN

// ---------------- scratch (device globals; no allocation allowed) ----------
__device__ __align__(16) float g_Ainv[NDIM * NDIM];
__device__ __align__(16) float g_p[TTOT * NDIM];      // p = x @ B_w^T
__device__ __align__(16) float g_hs[TTOT * NDIM];     // scan states

__device__ __forceinline__ float fast_exp2(float x) {
    float y;
    asm("ex2.approx.ftz.f32 %0, %1;" : "=f"(y) : "f"(x));
    return y;
}

// ===========================================================================
// kernel_prep: Gauss-Jordan inverse of A (64x64), partial pivoting,
// + one Newton refinement. 512 threads, 3 barriers/iter, float4 elimination.
// smem: M[64][132] (augmented [A|I]), X[64][68], R[64][68]
// ===========================================================================
#define PREP_SMEM_FLOATS (64*132 + 64*68 + 64*68)

__global__ void kernel_prep(const float* __restrict__ A) {
    extern __shared__ float sm[];
    float* M = sm;                 // 64 x 132
    float* X = M + 64 * 132;       // 64 x 68
    float* R = X + 64 * 68;        // 64 x 68
    __shared__ int s_piv;
    __shared__ float s_scale;
    const int tid = threadIdx.x;

    // load [A | I]
    for (int e = tid; e < 64 * 64; e += 512) {
        int i = e >> 6, j = e & 63;
        M[i * 132 + j] = A[e];
        M[i * 132 + 64 + j] = (i == j) ? 1.0f : 0.0f;
    }
    __syncthreads();

    const int cg = tid & 31;        // float4 column group: cols cg*4..cg*4+3
    const int rbase = tid >> 5;     // 0..15 ; rows rbase + 16*s

    for (int k = 0; k < 64; ++k) {
        // pivot search + scale (warp 0)
        if (tid < 32) {
            float best = -1.0f; int bi = k;
            for (int i = k + tid; i < 64; i += 32) {
                float v = fabsf(M[i * 132 + k]);
                if (v > best) { best = v; bi = i; }
            }
            #pragma unroll
            for (int off = 16; off > 0; off >>= 1) {
                float ob = __shfl_xor_sync(0xffffffffu, best, off);
                int obi  = __shfl_xor_sync(0xffffffffu, bi, off);
                if (ob > best) { best = ob; bi = obi; }
            }
            if (tid == 0) {
                s_piv = bi;
                s_scale = 1.0f / M[bi * 132 + k];
            }
        }
        __syncthreads();                       // b1
        const int piv = s_piv;
        const float scale = s_scale;
        // fused swap + scale of row k (threads 0..127)
        if (tid < 128) {
            int j = tid;
            float a = M[k * 132 + j];
            float b = M[piv * 132 + j];
            float rk = (piv != k) ? b : a;
            if (piv != k) M[piv * 132 + j] = a;
            M[k * 132 + j] = rk * scale;
        }
        __syncthreads();                       // b2
        // eliminate: each thread: 4 cols (cg) x 4 rows; col k preserved
        {
            float4 fk = *(const float4*)&M[k * 132 + cg * 4];
            const int kin = k - cg * 4;        // 0..3 if col k in this group
            #pragma unroll
            for (int s = 0; s < 4; ++s) {
                int i = rbase + 16 * s;
                if (i == k) continue;
                float mik = M[i * 132 + k];
                float4 vv = *(const float4*)&M[i * 132 + cg * 4];
                float4 nv;
                nv.x = fmaf(-mik, fk.x, vv.x);
                nv.y = fmaf(-mik, fk.y, vv.y);
                nv.z = fmaf(-mik, fk.z, vv.z);
                nv.w = fmaf(-mik, fk.w, vv.w);
                if (kin == 0) nv.x = vv.x;
                else if (kin == 1) nv.y = vv.y;
                else if (kin == 2) nv.z = vv.z;
                else if (kin == 3) nv.w = vv.w;
                *(float4*)&M[i * 132 + cg * 4] = nv;
            }
        }
        __syncthreads();                       // b3 (orders elim before next pivot)
    }

    // X = right half; reload A into left half
    for (int e = tid; e < 4096; e += 512) {
        int i = e >> 6, j = e & 63;
        X[i * 68 + j] = M[i * 132 + 64 + j];
    }
    __syncthreads();
    for (int e = tid; e < 4096; e += 512) {
        int i = e >> 6, j = e & 63;
        M[i * 132 + j] = A[e];
    }
    __syncthreads();

    // R = I - A*X
    for (int o = tid; o < 1024; o += 512) {
        int i = o >> 4, j4 = (o & 15) * 4;
        float4 acc;
        acc.x = (i == j4 + 0) ? 1.0f : 0.0f;
        acc.y = (i == j4 + 1) ? 1.0f : 0.0f;
        acc.z = (i == j4 + 2) ? 1.0f : 0.0f;
        acc.w = (i == j4 + 3) ? 1.0f : 0.0f;
        #pragma unroll 8
        for (int k2 = 0; k2 < 64; ++k2) {
            float a = M[i * 132 + k2];
            float4 xv = *(const float4*)&X[k2 * 68 + j4];
            acc.x = fmaf(-a, xv.x, acc.x);
            acc.y = fmaf(-a, xv.y, acc.y);
            acc.z = fmaf(-a, xv.z, acc.z);
            acc.w = fmaf(-a, xv.w, acc.w);
        }
        *(float4*)&R[i * 68 + j4] = acc;
    }
    __syncthreads();

    // Ainv = X + X*R
    for (int o = tid; o < 1024; o += 512) {
        int i = o >> 4, j4 = (o & 15) * 4;
        float4 acc = *(const float4*)&X[i * 68 + j4];
        #pragma unroll 8
        for (int k2 = 0; k2 < 64; ++k2) {
            float a = X[i * 68 + k2];
            float4 rv = *(const float4*)&R[k2 * 68 + j4];
            acc.x = fmaf(a, rv.x, acc.x);
            acc.y = fmaf(a, rv.y, acc.y);
            acc.z = fmaf(a, rv.z, acc.z);
            acc.w = fmaf(a, rv.w, acc.w);
        }
        *(float4*)&g_Ainv[i * 64 + j4] = acc;
    }
}

// ===========================================================================
// kernel_p: p = x @ B_w^T   (4096 x 64, K=512), NT GEMM.
// ===========================================================================
__global__ void kernel_p(const float* __restrict__ Xin, const float* __restrict__ Bw) {
    __shared__ float As[2][32][36];
    __shared__ float Bs[2][32][68];
    const int tid = threadIdx.x;
    const int m0 = blockIdx.x * 32;
    const int tx = tid & 15, ty = tid >> 4;

    const int ar  = tid >> 3;
    const int akq = (tid & 7) * 4;
    const int br0 = ar;
    const int br1 = 32 + ar;

    float acc[2][4] = {};
    float4 pa, pb0, pb1;

    pa  = *(const float4*)(Xin + (m0 + ar) * 512 + akq);
    pb0 = *(const float4*)(Bw + br0 * 512 + akq);
    pb1 = *(const float4*)(Bw + br1 * 512 + akq);
    As[0][akq+0][ar] = pa.x;  As[0][akq+1][ar] = pa.y;
    As[0][akq+2][ar] = pa.z;  As[0][akq+3][ar] = pa.w;
    Bs[0][akq+0][br0] = pb0.x; Bs[0][akq+1][br0] = pb0.y;
    Bs[0][akq+2][br0] = pb0.z; Bs[0][akq+3][br0] = pb0.w;
    Bs[0][akq+0][br1] = pb1.x; Bs[0][akq+1][br1] = pb1.y;
    Bs[0][akq+2][br1] = pb1.z; Bs[0][akq+3][br1] = pb1.w;
    __syncthreads();

    int buf = 0;
    for (int kt = 0; kt < 16; ++kt) {
        if (kt + 1 < 16) {
            int kk = (kt + 1) * 32;
            pa  = *(const float4*)(Xin + (m0 + ar) * 512 + kk + akq);
            pb0 = *(const float4*)(Bw + br0 * 512 + kk + akq);
            pb1 = *(const float4*)(Bw + br1 * 512 + kk + akq);
        }
        #pragma unroll
        for (int k = 0; k < 32; ++k) {
            float a0 = As[buf][k][ty * 2 + 0];
            float a1 = As[buf][k][ty * 2 + 1];
            float4 bv = *(const float4*)&Bs[buf][k][tx * 4];
            acc[0][0] = fmaf(a0, bv.x, acc[0][0]);
            acc[0][1] = fmaf(a0, bv.y, acc[0][1]);
            acc[0][2] = fmaf(a0, bv.z, acc[0][2]);
            acc[0][3] = fmaf(a0, bv.w, acc[0][3]);
            acc[1][0] = fmaf(a1, bv.x, acc[1][0]);
            acc[1][1] = fmaf(a1, bv.y, acc[1][1]);
            acc[1][2] = fmaf(a1, bv.z, acc[1][2]);
            acc[1][3] = fmaf(a1, bv.w, acc[1][3]);
        }
        if (kt + 1 < 16) {
            int nb = buf ^ 1;
            As[nb][akq+0][ar] = pa.x;  As[nb][akq+1][ar] = pa.y;
            As[nb][akq+2][ar] = pa.z;  As[nb][akq+3][ar] = pa.w;
            Bs[nb][akq+0][br0] = pb0.x; Bs[nb][akq+1][br0] = pb0.y;
            Bs[nb][akq+2][br0] = pb0.z; Bs[nb][akq+3][br0] = pb0.w;
            Bs[nb][akq+0][br1] = pb1.x; Bs[nb][akq+1][br1] = pb1.y;
            Bs[nb][akq+2][br1] = pb1.z; Bs[nb][akq+3][br1] = pb1.w;
            __syncthreads();
            buf = nb;
        }
    }

    #pragma unroll
    for (int i = 0; i < 2; ++i) {
        float4 o;
        o.x = acc[i][0]; o.y = acc[i][1]; o.z = acc[i][2]; o.w = acc[i][3];
        *(float4*)&g_p[(m0 + ty * 2 + i) * 64 + tx * 4] = o;
    }
}

// ===========================================================================
// kernel_scan: chunked selective scan, register-resident A slices.
// 128 blocks (32 steps + 8 warmup), 256 threads.
// Thread (q = tid>>6, n = tid&63) holds in registers:
//   aCol[i] = log2e*A[mb+i][n]  (for h @ A_bar term)
//   aRow[i] = log2e*A[n][mb+i]  (for A_bar @ v term)
//   aInv[i] = Ainv[n][mb+i]     (for v = Ainv @ p)
// where mb = q*16. Each A_bar element exp'd by exactly 2 threads; no smem
// for A_bar at all. 2 barriers per step; MUFU-bound (~512 cyc/step).
// ===========================================================================
#define SCAN_SMEM_FLOATS (40*64 + 40*64 + 4*40*64 + 64 + 256 + 64 + 16)

__global__ void kernel_scan(const float* __restrict__ A, const float* __restrict__ dlt) {
    extern __shared__ float sm[];
    float* sP     = sm;                    // 40*64
    float* sV     = sP + 40 * 64;          // 40*64
    float* sPartV = sV + 40 * 64;          // 4*40*64
    float* sDelta = sPartV + 4 * 40 * 64;  // 64
    float* sPart  = sDelta + 64;           // 4*64
    float* sH     = sPart + 256;           // 64 (16B aligned: offset multiple of 16 floats)

    const int tid = threadIdx.x;
    const int g = blockIdx.x;
    const int lc = g & 63;
    const int warm = lc ? 8 : 0;
    const int t0g = g * 32 - warm;
    const int nsteps = 32 + warm;

    const float LOG2E = 1.4426950408889634f;
    const int n = tid & 63, q = tid >> 6;
    const int mb = q * 16;

    // ---- register preloads (global, coalesced) ----
    float aCol[16], aRow[16], aInv[16];
    #pragma unroll
    for (int i = 0; i < 16; ++i) {
        aCol[i] = LOG2E * A[(mb + i) * 64 + n];
    }
    #pragma unroll
    for (int i4 = 0; i4 < 4; ++i4) {
        float4 r = *(const float4*)(A + n * 64 + mb + i4 * 4);
        aRow[i4*4+0] = LOG2E * r.x; aRow[i4*4+1] = LOG2E * r.y;
        aRow[i4*4+2] = LOG2E * r.z; aRow[i4*4+3] = LOG2E * r.w;
        float4 iv = *(const float4*)(g_Ainv + n * 64 + mb + i4 * 4);
        aInv[i4*4+0] = iv.x; aInv[i4*4+1] = iv.y;
        aInv[i4*4+2] = iv.z; aInv[i4*4+3] = iv.w;
    }

    // ---- stage p, delta ----
    for (int e = tid; e < nsteps * 64; e += 256) {
        sP[e] = g_p[t0g * 64 + e];
    }
    if (tid < nsteps) sDelta[tid] = dlt[t0g + tid];
    if (tid < 64) sH[tid] = 0.0f;
    __syncthreads();

    // ---- v[t][n] = sum_k Ainv[n][k] * p[t][k], split over q k-slices ----
    for (int t = 0; t < nsteps; ++t) {
        float acc = 0.0f;
        #pragma unroll
        for (int i4 = 0; i4 < 4; ++i4) {
            float4 pv = *(const float4*)&sP[t * 64 + mb + i4 * 4];
            acc = fmaf(aInv[i4*4+0], pv.x, acc);
            acc = fmaf(aInv[i4*4+1], pv.y, acc);
            acc = fmaf(aInv[i4*4+2], pv.z, acc);
            acc = fmaf(aInv[i4*4+3], pv.w, acc);
        }
        sPartV[q * (40 * 64) + t * 64 + n] = acc;
    }
    __syncthreads();
    for (int o = tid; o < nsteps * 64; o += 256) {
        sV[o] = sPartV[o] + sPartV[2560 + o] + sPartV[5120 + o] + sPartV[7680 + o];
    }
    __syncthreads();

    // ---- sequential steps ----
    for (int j = 0; j < nsteps; ++j) {
        const float dj = sDelta[j];
        float h[16], v[16];
        #pragma unroll
        for (int i4 = 0; i4 < 4; ++i4) {
            float4 hv = *(const float4*)&sH[mb + i4 * 4];
            h[i4*4+0] = hv.x; h[i4*4+1] = hv.y; h[i4*4+2] = hv.z; h[i4*4+3] = hv.w;
            float4 vv = *(const float4*)&sV[j * 64 + mb + i4 * 4];
            v[i4*4+0] = vv.x; v[i4*4+1] = vv.y; v[i4*4+2] = vv.z; v[i4*4+3] = vv.w;
        }
        float acc = 0.0f;
        #pragma unroll
        for (int i = 0; i < 16; ++i) {
            acc = fmaf(h[i], fast_exp2(dj * aCol[i]), acc);
            acc = fmaf(fast_exp2(dj * aRow[i]), v[i], acc);
        }
        sPart[q * 64 + n] = acc;
        __syncthreads();
        if (tid < 64) {
            float hn = sPart[tid] + sPart[64 + tid] + sPart[128 + tid] + sPart[192 + tid]
                       - sV[j * 64 + tid];
            sH[tid] = hn;
            if (j >= warm) g_hs[(t0g + j) * 64 + tid] = hn;
        }
        __syncthreads();
    }
}

// ===========================================================================
// kernel_y1: Y = x @ D_w^T + (C_b + D_b).  M=4096, N=512, K=512.
// ===========================================================================
__global__ void kernel_y1(const float* __restrict__ Xin, const float* __restrict__ Dw,
                          const float* __restrict__ Cb, const float* __restrict__ Db,
                          float* __restrict__ Y) {
    __shared__ float As[2][16][132];
    __shared__ float Bs[2][16][132];
    const int tid = threadIdx.x;
    const int m0 = blockIdx.y * 128;
    const int n0 = blockIdx.x * 128;

    const int r0 = tid >> 2;
    const int r1 = 64 + r0;
    const int kq = (tid & 3) * 4;

    const int w = tid >> 5, lane = tid & 31;
    const int wm = w & 3, wn = w >> 2;
    const int r = lane >> 3, c = lane & 7;
    const int aoff = wm * 32 + r * 8;
    const int boff0 = wn * 64 + c * 4;
    const int boff1 = boff0 + 32;

    float acc[8][8] = {};
    float4 pa0, pa1, pb0, pb1;

    auto fetch = [&](int kt) {
        int kk = kt * 16;
        pa0 = *(const float4*)(Xin + (m0 + r0) * 512 + kk + kq);
        pa1 = *(const float4*)(Xin + (m0 + r1) * 512 + kk + kq);
        pb0 = *(const float4*)(Dw + (n0 + r0) * 512 + kk + kq);
        pb1 = *(const float4*)(Dw + (n0 + r1) * 512 + kk + kq);
    };
    auto stash = [&](int b) {
        As[b][kq+0][r0] = pa0.x; As[b][kq+1][r0] = pa0.y;
        As[b][kq+2][r0] = pa0.z; As[b][kq+3][r0] = pa0.w;
        As[b][kq+0][r1] = pa1.x; As[b][kq+1][r1] = pa1.y;
        As[b][kq+2][r1] = pa1.z; As[b][kq+3][r1] = pa1.w;
        Bs[b][kq+0][r0] = pb0.x; Bs[b][kq+1][r0] = pb0.y;
        Bs[b][kq+2][r0] = pb0.z; Bs[b][kq+3][r0] = pb0.w;
        Bs[b][kq+0][r1] = pb1.x; Bs[b][kq+1][r1] = pb1.y;
        Bs[b][kq+2][r1] = pb1.z; Bs[b][kq+3][r1] = pb1.w;
    };

    fetch(0);
    stash(0);
    __syncthreads();

    int buf = 0;
    for (int kt = 0; kt < 32; ++kt) {
        if (kt + 1 < 32) fetch(kt + 1);
        #pragma unroll
        for (int k = 0; k < 16; ++k) {
            float4 a0 = *(const float4*)&As[buf][k][aoff];
            float4 a1 = *(const float4*)&As[buf][k][aoff + 4];
            float4 b0 = *(const float4*)&Bs[buf][k][boff0];
            float4 b1 = *(const float4*)&Bs[buf][k][boff1];
            float av[8] = {a0.x, a0.y, a0.z, a0.w, a1.x, a1.y, a1.z, a1.w};
            float bv[8] = {b0.x, b0.y, b0.z, b0.w, b1.x, b1.y, b1.z, b1.w};
            #pragma unroll
            for (int i = 0; i < 8; ++i) {
                #pragma unroll
                for (int jj = 0; jj < 8; ++jj) {
                    acc[i][jj] = fmaf(av[i], bv[jj], acc[i][jj]);
                }
            }
        }
        if (kt + 1 < 32) {
            stash(buf ^ 1);
            __syncthreads();
            buf ^= 1;
        }
    }

    const int cg0 = n0 + boff0;
    const int cg1 = n0 + boff1;
    float4 cb0 = *(const float4*)(Cb + cg0);
    float4 db0 = *(const float4*)(Db + cg0);
    float4 cb1 = *(const float4*)(Cb + cg1);
    float4 db1 = *(const float4*)(Db + cg1);
    float4 bia0 = {cb0.x + db0.x, cb0.y + db0.y, cb0.z + db0.z, cb0.w + db0.w};
    float4 bia1 = {cb1.x + db1.x, cb1.y + db1.y, cb1.z + db1.z, cb1.w + db1.w};

    #pragma unroll
    for (int i = 0; i < 8; ++i) {
        int gm = m0 + aoff + i;
        float4 o0 = {acc[i][0] + bia0.x, acc[i][1] + bia0.y,
                     acc[i][2] + bia0.z, acc[i][3] + bia0.w};
        float4 o1 = {acc[i][4] + bia1.x, acc[i][5] + bia1.y,
                     acc[i][6] + bia1.z, acc[i][7] + bia1.w};
        *(float4*)(Y + gm * 512 + cg0) = o0;
        *(float4*)(Y + gm * 512 + cg1) = o1;
    }
}

// ===========================================================================
// kernel_y2: Y += hs @ C_w^T.  M=4096, N=512, K=64.
// ===========================================================================
__global__ void kernel_y2(const float* __restrict__ Cw, float* __restrict__ Y) {
    __shared__ float As[2][16][132];
    __shared__ float Bs[2][16][132];
    const int tid = threadIdx.x;
    const int m0 = blockIdx.y * 128;
    const int n0 = blockIdx.x * 128;

    const int r0 = tid >> 2;
    const int r1 = 64 + r0;
    const int kq = (tid & 3) * 4;

    const int w = tid >> 5, lane = tid & 31;
    const int wm = w & 3, wn = w >> 2;
    const int r = lane >> 3, c = lane & 7;
    const int aoff = wm * 32 + r * 8;
    const int boff0 = wn * 64 + c * 4;
    const int boff1 = boff0 + 32;

    float acc[8][8] = {};
    float4 pa0, pa1, pb0, pb1;

    auto fetch = [&](int kt) {
        int kk = kt * 16;
        pa0 = *(const float4*)(g_hs + (m0 + r0) * 64 + kk + kq);
        pa1 = *(const float4*)(g_hs + (m0 + r1) * 64 + kk + kq);
        pb0 = *(const float4*)(Cw + (n0 + r0) * 64 + kk + kq);
        pb1 = *(const float4*)(Cw + (n0 + r1) * 64 + kk + kq);
    };
    auto stash = [&](int b) {
        As[b][kq+0][r0] = pa0.x; As[b][kq+1][r0] = pa0.y;
        As[b][kq+2][r0] = pa0.z; As[b][kq+3][r0] = pa0.w;
        As[b][kq+0][r1] = pa1.x; As[b][kq+1][r1] = pa1.y;
        As[b][kq+2][r1] = pa1.z; As[b][kq+3][r1] = pa1.w;
        Bs[b][kq+0][r0] = pb0.x; Bs[b][kq+1][r0] = pb0.y;
        Bs[b][kq+2][r0] = pb0.z; Bs[b][kq+3][r0] = pb0.w;
        Bs[b][kq+0][r1] = pb1.x; Bs[b][kq+1][r1] = pb1.y;
        Bs[b][kq+2][r1] = pb1.z; Bs[b][kq+3][r1] = pb1.w;
    };

    fetch(0);
    stash(0);
    __syncthreads();

    int buf = 0;
    for (int kt = 0; kt < 4; ++kt) {
        if (kt + 1 < 4) fetch(kt + 1);
        #pragma unroll
        for (int k = 0; k < 16; ++k) {
            float4 a0 = *(const float4*)&As[buf][k][aoff];
            float4 a1 = *(const float4*)&As[buf][k][aoff + 4];
            float4 b0 = *(const float4*)&Bs[buf][k][boff0];
            float4 b1 = *(const float4*)&Bs[buf][k][boff1];
            float av[8] = {a0.x, a0.y, a0.z, a0.w, a1.x, a1.y, a1.z, a1.w};
            float bv[8] = {b0.x, b0.y, b0.z, b0.w, b1.x, b1.y, b1.z, b1.w};
            #pragma unroll
            for (int i = 0; i < 8; ++i) {
                #pragma unroll
                for (int jj = 0; jj < 8; ++jj) {
                    acc[i][jj] = fmaf(av[i], bv[jj], acc[i][jj]);
                }
            }
        }
        if (kt + 1 < 4) {
            stash(buf ^ 1);
            __syncthreads();
            buf ^= 1;
        }
    }

    const int cg0 = n0 + boff0;
    const int cg1 = n0 + boff1;
    #pragma unroll
    for (int i = 0; i < 8; ++i) {
        int gm = m0 + aoff + i;
        float4 y0 = *(const float4*)(Y + gm * 512 + cg0);
        float4 y1 = *(const float4*)(Y + gm * 512 + cg1);
        y0.x += acc[i][0]; y0.y += acc[i][1]; y0.z += acc[i][2]; y0.w += acc[i][3];
        y1.x += acc[i][4]; y1.y += acc[i][5]; y1.z += acc[i][6]; y1.w += acc[i][7];
        *(float4*)(Y + gm * 512 + cg0) = y0;
        *(float4*)(Y + gm * 512 + cg1) = y1;
    }
}

// ===========================================================================
// Stream/event context: created once on the first (correctness) call,
// which happens before graph capture. Topology identical on every call.
// ===========================================================================
struct LaunchCtx {
    cudaStream_t s1, s2;
    cudaEvent_t e_root, e_prep, e_y1;
    LaunchCtx() {
        cudaStreamCreateWithFlags(&s1, cudaStreamNonBlocking);
        cudaStreamCreateWithFlags(&s2, cudaStreamNonBlocking);
        cudaEventCreateWithFlags(&e_root, cudaEventDisableTiming);
        cudaEventCreateWithFlags(&e_prep, cudaEventDisableTiming);
        cudaEventCreateWithFlags(&e_y1, cudaEventDisableTiming);
    }
};

extern "C" void kernel_launch(void* const* d_in, const int* in_sizes, int n_in,
                              void* d_out, int out_size) {
    const float* x   = (const float*)d_in[0];   // (B,S,H)
    const float* dlt = (const float*)d_in[1];   // (B,S)
    const float* A   = (const float*)d_in[2];   // (N,N)
    const float* Bw  = (const float*)d_in[3];   // (N,H)
    const float* Cw  = (const float*)d_in[4];   // (H,N)
    const float* Cb  = (const float*)d_in[5];   // (H)
    const float* Dw  = (const float*)d_in[6];   // (H,H)
    const float* Db  = (const float*)d_in[7];   // (H)
    float* Y = (float*)d_out;

    static LaunchCtx ctx;

    const int prep_smem = PREP_SMEM_FLOATS * 4;
    const int scan_smem = SCAN_SMEM_FLOATS * 4;
    cudaFuncSetAttribute(kernel_prep, cudaFuncAttributeMaxDynamicSharedMemorySize, prep_smem);
    cudaFuncSetAttribute(kernel_scan, cudaFuncAttributeMaxDynamicSharedMemorySize, scan_smem);

    // Fork: s1 (prep), s2 (y1) branch off the main stream.
    cudaEventRecord(ctx.e_root, 0);
    cudaStreamWaitEvent(ctx.s1, ctx.e_root, 0);
    cudaStreamWaitEvent(ctx.s2, ctx.e_root, 0);

    kernel_y1<<<dim3(4, 32), 256, 0, ctx.s2>>>(x, Dw, Cb, Db, Y);   // critical path
    cudaEventRecord(ctx.e_y1, ctx.s2);

    kernel_prep<<<1, 512, prep_smem, ctx.s1>>>(A);
    cudaEventRecord(ctx.e_prep, ctx.s1);

    kernel_p<<<128, 256>>>(x, Bw);                 // main stream
    cudaStreamWaitEvent(0, ctx.e_prep, 0);         // scan needs Ainv + p
    kernel_scan<<<128, 256, scan_smem>>>(A, dlt);
    cudaStreamWaitEvent(0, ctx.e_y1, 0);           // y2 accumulates into Y
    kernel_y2<<<dim3(4, 32), 256>>>(Cw, Y);
}

// round 6
// speedup vs baseline: 2.0634x; 1.4157x over previous
#include <cuda_runtime.h>
#include <cuda_bf16.h>
#include <cstdint>

// Problem dims
#define BSZ 2
#define SLEN 2048
#define HDIM 512
#define NDIM 64
#define TTOT 4096   // BSZ*SLEN

// ---------------- scratch (device globals; no allocation allowed) ----------
__device__ __align__(16) float g_Ainv[NDIM * NDIM];
__device__ __align__(16) float g_p[TTOT * NDIM];      // p = x @ B_w^T
__device__ __align__(16) float g_hs[TTOT * NDIM];     // scan states
__device__ __align__(16) __nv_bfloat16 g_xh[TTOT * HDIM];   // x hi split
__device__ __align__(16) __nv_bfloat16 g_xl[TTOT * HDIM];   // x lo split
__device__ __align__(16) __nv_bfloat16 g_wh[HDIM * HDIM];   // Dw hi split
__device__ __align__(16) __nv_bfloat16 g_wl[HDIM * HDIM];   // Dw lo split

__device__ __forceinline__ float fast_exp2(float x) {
    float y;
    asm("ex2.approx.ftz.f32 %0, %1;" : "=f"(y) : "f"(x));
    return y;
}

__device__ __forceinline__ uint32_t smem_u32(const void* p) {
    return (uint32_t)__cvta_generic_to_shared(p);
}

__device__ __forceinline__ void ldsm4(uint32_t* r, uint32_t a) {
    asm volatile("ldmatrix.sync.aligned.m8n8.x4.shared.b16 {%0,%1,%2,%3}, [%4];"
                 : "=r"(r[0]), "=r"(r[1]), "=r"(r[2]), "=r"(r[3]) : "r"(a));
}
__device__ __forceinline__ void ldsm2(uint32_t* r, uint32_t a) {
    asm volatile("ldmatrix.sync.aligned.m8n8.x2.shared.b16 {%0,%1}, [%2];"
                 : "=r"(r[0]), "=r"(r[1]) : "r"(a));
}
__device__ __forceinline__ void mma16816(float* d, const uint32_t* a, const uint32_t* b) {
    asm volatile(
        "mma.sync.aligned.m16n8k16.row.col.f32.bf16.bf16.f32 "
        "{%0,%1,%2,%3}, {%4,%5,%6,%7}, {%8,%9}, {%0,%1,%2,%3};"
        : "+f"(d[0]), "+f"(d[1]), "+f"(d[2]), "+f"(d[3])
        : "r"(a[0]), "r"(a[1]), "r"(a[2]), "r"(a[3]), "r"(b[0]), "r"(b[1]));
}

// ===========================================================================
// kernel_conv_x / kernel_conv_w: fp32 -> (hi, lo) bf16 splits.
// ===========================================================================
__global__ void kernel_conv_x(const float* __restrict__ x) {
    int i = (blockIdx.x * 256 + threadIdx.x) * 4;           // 2M elems / 4
    float4 v = *(const float4*)(x + i);
    __nv_bfloat16 h0 = __float2bfloat16(v.x);
    __nv_bfloat16 h1 = __float2bfloat16(v.y);
    __nv_bfloat16 h2 = __float2bfloat16(v.z);
    __nv_bfloat16 h3 = __float2bfloat16(v.w);
    __nv_bfloat16 l0 = __float2bfloat16(v.x - __bfloat162float(h0));
    __nv_bfloat16 l1 = __float2bfloat16(v.y - __bfloat162float(h1));
    __nv_bfloat16 l2 = __float2bfloat16(v.z - __bfloat162float(h2));
    __nv_bfloat16 l3 = __float2bfloat16(v.w - __bfloat162float(h3));
    *(__nv_bfloat162*)&g_xh[i + 0] = __halves2bfloat162(h0, h1);
    *(__nv_bfloat162*)&g_xh[i + 2] = __halves2bfloat162(h2, h3);
    *(__nv_bfloat162*)&g_xl[i + 0] = __halves2bfloat162(l0, l1);
    *(__nv_bfloat162*)&g_xl[i + 2] = __halves2bfloat162(l2, l3);
}
__global__ void kernel_conv_w(const float* __restrict__ w) {
    int i = (blockIdx.x * 256 + threadIdx.x) * 4;           // 256K elems / 4
    float4 v = *(const float4*)(w + i);
    __nv_bfloat16 h0 = __float2bfloat16(v.x);
    __nv_bfloat16 h1 = __float2bfloat16(v.y);
    __nv_bfloat16 h2 = __float2bfloat16(v.z);
    __nv_bfloat16 h3 = __float2bfloat16(v.w);
    __nv_bfloat16 l0 = __float2bfloat16(v.x - __bfloat162float(h0));
    __nv_bfloat16 l1 = __float2bfloat16(v.y - __bfloat162float(h1));
    __nv_bfloat16 l2 = __float2bfloat16(v.z - __bfloat162float(h2));
    __nv_bfloat16 l3 = __float2bfloat16(v.w - __bfloat162float(h3));
    *(__nv_bfloat162*)&g_wh[i + 0] = __halves2bfloat162(h0, h1);
    *(__nv_bfloat162*)&g_wh[i + 2] = __halves2bfloat162(h2, h3);
    *(__nv_bfloat162*)&g_wl[i + 0] = __halves2bfloat162(l0, l1);
    *(__nv_bfloat162*)&g_wl[i + 2] = __halves2bfloat162(l2, l3);
}

// ===========================================================================
// kernel_y1_mma: Y = x @ Dw^T + (Cb+Db), bf16 tensor-core 2-way split.
// y ~= xh*wh + xh*wl + xl*wh  (xl*wl dropped, ~2^-16 relative).
// BM=BN=128, BK=32, 256 thr = 8 warps (2x4), warp tile 64x32,
// m16n8k16 mma, ldmatrix from padded smem (stride 40 bf16 = 80 B rows).
// grid (4, 32). Dynamic smem: 4 arrays x 2 buffers x 128x40 bf16 = 80 KB.
// ===========================================================================
#define Y1_TS (128 * 40)
#define Y1_SMEM_BYTES (8 * Y1_TS * 2)

__global__ __launch_bounds__(256, 1)
void kernel_y1_mma(const float* __restrict__ Cb, const float* __restrict__ Db,
                   float* __restrict__ Y) {
    extern __shared__ __nv_bfloat16 smem[];
    __nv_bfloat16* sAh = smem;                // [2][Y1_TS]
    __nv_bfloat16* sAl = smem + 2 * Y1_TS;
    __nv_bfloat16* sBh = smem + 4 * Y1_TS;
    __nv_bfloat16* sBl = smem + 6 * Y1_TS;

    const int tid = threadIdx.x;
    const int m0 = blockIdx.y * 128;
    const int n0 = blockIdx.x * 128;

    // tile loader mapping: 128 rows x 32 k; thread -> rows (lrow, lrow+64), 8 bf16 chunk
    const int lrow = tid >> 2;            // 0..63
    const int lch  = (tid & 3) * 8;       // bf16 col offset 0,8,16,24

    // compute mapping
    const int lane = tid & 31;
    const int w = tid >> 5;
    const int wm = w & 1;                 // 2 in M
    const int wn = w >> 1;                // 4 in N
    const int a_row = wm * 64 + (lane & 15);
    const int a_col = (lane >> 4) * 8;
    const int b_row = wn * 32 + (lane & 7);
    const int b_col = ((lane >> 3) & 1) * 8;

    float acc[4][4][4] = {};

    uint4 pAh0, pAh1, pAl0, pAl1, pBh0, pBh1, pBl0, pBl1;
    auto fetch = [&](int kt) {
        const int kk = kt * 32 + lch;
        pAh0 = *(const uint4*)&g_xh[(m0 + lrow) * 512 + kk];
        pAh1 = *(const uint4*)&g_xh[(m0 + lrow + 64) * 512 + kk];
        pAl0 = *(const uint4*)&g_xl[(m0 + lrow) * 512 + kk];
        pAl1 = *(const uint4*)&g_xl[(m0 + lrow + 64) * 512 + kk];
        pBh0 = *(const uint4*)&g_wh[(n0 + lrow) * 512 + kk];
        pBh1 = *(const uint4*)&g_wh[(n0 + lrow + 64) * 512 + kk];
        pBl0 = *(const uint4*)&g_wl[(n0 + lrow) * 512 + kk];
        pBl1 = *(const uint4*)&g_wl[(n0 + lrow + 64) * 512 + kk];
    };
    auto stash = [&](int b) {
        const int o0 = b * Y1_TS + lrow * 40 + lch;
        const int o1 = b * Y1_TS + (lrow + 64) * 40 + lch;
        *(uint4*)&sAh[o0] = pAh0;  *(uint4*)&sAh[o1] = pAh1;
        *(uint4*)&sAl[o0] = pAl0;  *(uint4*)&sAl[o1] = pAl1;
        *(uint4*)&sBh[o0] = pBh0;  *(uint4*)&sBh[o1] = pBh1;
        *(uint4*)&sBl[o0] = pBl0;  *(uint4*)&sBl[o1] = pBl1;
    };

    fetch(0);
    stash(0);
    __syncthreads();

    int buf = 0;
    for (int kt = 0; kt < 16; ++kt) {
        if (kt + 1 < 16) fetch(kt + 1);
        const __nv_bfloat16* bAh = sAh + buf * Y1_TS;
        const __nv_bfloat16* bAl = sAl + buf * Y1_TS;
        const __nv_bfloat16* bBh = sBh + buf * Y1_TS;
        const __nv_bfloat16* bBl = sBl + buf * Y1_TS;
        #pragma unroll
        for (int k16 = 0; k16 < 2; ++k16) {
            uint32_t ah[4][4], al[4][4], bh[4][2], bl[4][2];
            #pragma unroll
            for (int mi = 0; mi < 4; ++mi) {
                ldsm4(ah[mi], smem_u32(bAh + (a_row + mi * 16) * 40 + a_col + k16 * 16));
                ldsm4(al[mi], smem_u32(bAl + (a_row + mi * 16) * 40 + a_col + k16 * 16));
            }
            #pragma unroll
            for (int ni = 0; ni < 4; ++ni) {
                ldsm2(bh[ni], smem_u32(bBh + (b_row + ni * 8) * 40 + b_col + k16 * 16));
                ldsm2(bl[ni], smem_u32(bBl + (b_row + ni * 8) * 40 + b_col + k16 * 16));
            }
            #pragma unroll
            for (int mi = 0; mi < 4; ++mi) {
                #pragma unroll
                for (int ni = 0; ni < 4; ++ni) {
                    mma16816(acc[mi][ni], ah[mi], bh[ni]);
                    mma16816(acc[mi][ni], ah[mi], bl[ni]);
                    mma16816(acc[mi][ni], al[mi], bh[ni]);
                }
            }
        }
        if (kt + 1 < 16) {
            stash(buf ^ 1);
            __syncthreads();
            buf ^= 1;
        }
    }

    // epilogue: bias + store
    #pragma unroll
    for (int ni = 0; ni < 4; ++ni) {
        const int gn = n0 + wn * 32 + ni * 8 + (lane & 3) * 2;
        float2 cb = *(const float2*)(Cb + gn);
        float2 db = *(const float2*)(Db + gn);
        const float bx = cb.x + db.x, by = cb.y + db.y;
        #pragma unroll
        for (int mi = 0; mi < 4; ++mi) {
            const int gm = m0 + wm * 64 + mi * 16 + (lane >> 2);
            float2 o0 = {acc[mi][ni][0] + bx, acc[mi][ni][1] + by};
            float2 o1 = {acc[mi][ni][2] + bx, acc[mi][ni][3] + by};
            *(float2*)(Y + gm * 512 + gn) = o0;
            *(float2*)(Y + (gm + 8) * 512 + gn) = o1;
        }
    }
}

// ===========================================================================
// kernel_prep: Gauss-Jordan inverse of A (64x64), partial pivoting,
// + one Newton refinement. 512 threads.
// ===========================================================================
#define PREP_SMEM_FLOATS (64*132 + 64*68 + 64*68)

__global__ void kernel_prep(const float* __restrict__ A) {
    extern __shared__ float sm[];
    float* M = sm;                 // 64 x 132
    float* X = M + 64 * 132;       // 64 x 68
    float* R = X + 64 * 68;        // 64 x 68
    __shared__ int s_piv;
    __shared__ float s_scale;
    const int tid = threadIdx.x;

    for (int e = tid; e < 64 * 64; e += 512) {
        int i = e >> 6, j = e & 63;
        M[i * 132 + j] = A[e];
        M[i * 132 + 64 + j] = (i == j) ? 1.0f : 0.0f;
    }
    __syncthreads();

    const int cg = tid & 31;
    const int rbase = tid >> 5;

    for (int k = 0; k < 64; ++k) {
        if (tid < 32) {
            float best = -1.0f; int bi = k;
            for (int i = k + tid; i < 64; i += 32) {
                float v = fabsf(M[i * 132 + k]);
                if (v > best) { best = v; bi = i; }
            }
            #pragma unroll
            for (int off = 16; off > 0; off >>= 1) {
                float ob = __shfl_xor_sync(0xffffffffu, best, off);
                int obi  = __shfl_xor_sync(0xffffffffu, bi, off);
                if (ob > best) { best = ob; bi = obi; }
            }
            if (tid == 0) {
                s_piv = bi;
                s_scale = 1.0f / M[bi * 132 + k];
            }
        }
        __syncthreads();
        const int piv = s_piv;
        const float scale = s_scale;
        if (tid < 128) {
            int j = tid;
            float a = M[k * 132 + j];
            float b = M[piv * 132 + j];
            float rk = (piv != k) ? b : a;
            if (piv != k) M[piv * 132 + j] = a;
            M[k * 132 + j] = rk * scale;
        }
        __syncthreads();
        {
            float4 fk = *(const float4*)&M[k * 132 + cg * 4];
            const int kin = k - cg * 4;
            #pragma unroll
            for (int s = 0; s < 4; ++s) {
                int i = rbase + 16 * s;
                if (i == k) continue;
                float mik = M[i * 132 + k];
                float4 vv = *(const float4*)&M[i * 132 + cg * 4];
                float4 nv;
                nv.x = fmaf(-mik, fk.x, vv.x);
                nv.y = fmaf(-mik, fk.y, vv.y);
                nv.z = fmaf(-mik, fk.z, vv.z);
                nv.w = fmaf(-mik, fk.w, vv.w);
                if (kin == 0) nv.x = vv.x;
                else if (kin == 1) nv.y = vv.y;
                else if (kin == 2) nv.z = vv.z;
                else if (kin == 3) nv.w = vv.w;
                *(float4*)&M[i * 132 + cg * 4] = nv;
            }
        }
        __syncthreads();
    }

    for (int e = tid; e < 4096; e += 512) {
        int i = e >> 6, j = e & 63;
        X[i * 68 + j] = M[i * 132 + 64 + j];
    }
    __syncthreads();
    for (int e = tid; e < 4096; e += 512) {
        int i = e >> 6, j = e & 63;
        M[i * 132 + j] = A[e];
    }
    __syncthreads();

    for (int o = tid; o < 1024; o += 512) {
        int i = o >> 4, j4 = (o & 15) * 4;
        float4 acc;
        acc.x = (i == j4 + 0) ? 1.0f : 0.0f;
        acc.y = (i == j4 + 1) ? 1.0f : 0.0f;
        acc.z = (i == j4 + 2) ? 1.0f : 0.0f;
        acc.w = (i == j4 + 3) ? 1.0f : 0.0f;
        #pragma unroll 8
        for (int k2 = 0; k2 < 64; ++k2) {
            float a = M[i * 132 + k2];
            float4 xv = *(const float4*)&X[k2 * 68 + j4];
            acc.x = fmaf(-a, xv.x, acc.x);
            acc.y = fmaf(-a, xv.y, acc.y);
            acc.z = fmaf(-a, xv.z, acc.z);
            acc.w = fmaf(-a, xv.w, acc.w);
        }
        *(float4*)&R[i * 68 + j4] = acc;
    }
    __syncthreads();

    for (int o = tid; o < 1024; o += 512) {
        int i = o >> 4, j4 = (o & 15) * 4;
        float4 acc = *(const float4*)&X[i * 68 + j4];
        #pragma unroll 8
        for (int k2 = 0; k2 < 64; ++k2) {
            float a = X[i * 68 + k2];
            float4 rv = *(const float4*)&R[k2 * 68 + j4];
            acc.x = fmaf(a, rv.x, acc.x);
            acc.y = fmaf(a, rv.y, acc.y);
            acc.z = fmaf(a, rv.z, acc.z);
            acc.w = fmaf(a, rv.w, acc.w);
        }
        *(float4*)&g_Ainv[i * 64 + j4] = acc;
    }
}

// ===========================================================================
// kernel_p: p = x @ B_w^T   (4096 x 64, K=512), NT GEMM.
// ===========================================================================
__global__ void kernel_p(const float* __restrict__ Xin, const float* __restrict__ Bw) {
    __shared__ float As[2][32][36];
    __shared__ float Bs[2][32][68];
    const int tid = threadIdx.x;
    const int m0 = blockIdx.x * 32;
    const int tx = tid & 15, ty = tid >> 4;

    const int ar  = tid >> 3;
    const int akq = (tid & 7) * 4;
    const int br0 = ar;
    const int br1 = 32 + ar;

    float acc[2][4] = {};
    float4 pa, pb0, pb1;

    pa  = *(const float4*)(Xin + (m0 + ar) * 512 + akq);
    pb0 = *(const float4*)(Bw + br0 * 512 + akq);
    pb1 = *(const float4*)(Bw + br1 * 512 + akq);
    As[0][akq+0][ar] = pa.x;  As[0][akq+1][ar] = pa.y;
    As[0][akq+2][ar] = pa.z;  As[0][akq+3][ar] = pa.w;
    Bs[0][akq+0][br0] = pb0.x; Bs[0][akq+1][br0] = pb0.y;
    Bs[0][akq+2][br0] = pb0.z; Bs[0][akq+3][br0] = pb0.w;
    Bs[0][akq+0][br1] = pb1.x; Bs[0][akq+1][br1] = pb1.y;
    Bs[0][akq+2][br1] = pb1.z; Bs[0][akq+3][br1] = pb1.w;
    __syncthreads();

    int buf = 0;
    for (int kt = 0; kt < 16; ++kt) {
        if (kt + 1 < 16) {
            int kk = (kt + 1) * 32;
            pa  = *(const float4*)(Xin + (m0 + ar) * 512 + kk + akq);
            pb0 = *(const float4*)(Bw + br0 * 512 + kk + akq);
            pb1 = *(const float4*)(Bw + br1 * 512 + kk + akq);
        }
        #pragma unroll
        for (int k = 0; k < 32; ++k) {
            float a0 = As[buf][k][ty * 2 + 0];
            float a1 = As[buf][k][ty * 2 + 1];
            float4 bv = *(const float4*)&Bs[buf][k][tx * 4];
            acc[0][0] = fmaf(a0, bv.x, acc[0][0]);
            acc[0][1] = fmaf(a0, bv.y, acc[0][1]);
            acc[0][2] = fmaf(a0, bv.z, acc[0][2]);
            acc[0][3] = fmaf(a0, bv.w, acc[0][3]);
            acc[1][0] = fmaf(a1, bv.x, acc[1][0]);
            acc[1][1] = fmaf(a1, bv.y, acc[1][1]);
            acc[1][2] = fmaf(a1, bv.z, acc[1][2]);
            acc[1][3] = fmaf(a1, bv.w, acc[1][3]);
        }
        if (kt + 1 < 16) {
            int nb = buf ^ 1;
            As[nb][akq+0][ar] = pa.x;  As[nb][akq+1][ar] = pa.y;
            As[nb][akq+2][ar] = pa.z;  As[nb][akq+3][ar] = pa.w;
            Bs[nb][akq+0][br0] = pb0.x; Bs[nb][akq+1][br0] = pb0.y;
            Bs[nb][akq+2][br0] = pb0.z; Bs[nb][akq+3][br0] = pb0.w;
            Bs[nb][akq+0][br1] = pb1.x; Bs[nb][akq+1][br1] = pb1.y;
            Bs[nb][akq+2][br1] = pb1.z; Bs[nb][akq+3][br1] = pb1.w;
            __syncthreads();
            buf = nb;
        }
    }

    #pragma unroll
    for (int i = 0; i < 2; ++i) {
        float4 o;
        o.x = acc[i][0]; o.y = acc[i][1]; o.z = acc[i][2]; o.w = acc[i][3];
        *(float4*)&g_p[(m0 + ty * 2 + i) * 64 + tx * 4] = o;
    }
}

// ===========================================================================
// kernel_scan: chunked selective scan, register-resident A slices.
// 128 blocks (32 steps + 8 warmup), 256 threads.
// ===========================================================================
#define SCAN_SMEM_FLOATS (40*64 + 40*64 + 4*40*64 + 64 + 256 + 64 + 16)

__global__ void kernel_scan(const float* __restrict__ A, const float* __restrict__ dlt) {
    extern __shared__ float sm[];
    float* sP     = sm;                    // 40*64
    float* sV     = sP + 40 * 64;          // 40*64
    float* sPartV = sV + 40 * 64;          // 4*40*64
    float* sDelta = sPartV + 4 * 40 * 64;  // 64
    float* sPart  = sDelta + 64;           // 4*64
    float* sH     = sPart + 256;           // 64

    const int tid = threadIdx.x;
    const int g = blockIdx.x;
    const int lc = g & 63;
    const int warm = lc ? 8 : 0;
    const int t0g = g * 32 - warm;
    const int nsteps = 32 + warm;

    const float LOG2E = 1.4426950408889634f;
    const int n = tid & 63, q = tid >> 6;
    const int mb = q * 16;

    float aCol[16], aRow[16], aInv[16];
    #pragma unroll
    for (int i = 0; i < 16; ++i) {
        aCol[i] = LOG2E * A[(mb + i) * 64 + n];
    }
    #pragma unroll
    for (int i4 = 0; i4 < 4; ++i4) {
        float4 r = *(const float4*)(A + n * 64 + mb + i4 * 4);
        aRow[i4*4+0] = LOG2E * r.x; aRow[i4*4+1] = LOG2E * r.y;
        aRow[i4*4+2] = LOG2E * r.z; aRow[i4*4+3] = LOG2E * r.w;
        float4 iv = *(const float4*)(g_Ainv + n * 64 + mb + i4 * 4);
        aInv[i4*4+0] = iv.x; aInv[i4*4+1] = iv.y;
        aInv[i4*4+2] = iv.z; aInv[i4*4+3] = iv.w;
    }

    for (int e = tid; e < nsteps * 64; e += 256) {
        sP[e] = g_p[t0g * 64 + e];
    }
    if (tid < nsteps) sDelta[tid] = dlt[t0g + tid];
    if (tid < 64) sH[tid] = 0.0f;
    __syncthreads();

    for (int t = 0; t < nsteps; ++t) {
        float acc = 0.0f;
        #pragma unroll
        for (int i4 = 0; i4 < 4; ++i4) {
            float4 pv = *(const float4*)&sP[t * 64 + mb + i4 * 4];
            acc = fmaf(aInv[i4*4+0], pv.x, acc);
            acc = fmaf(aInv[i4*4+1], pv.y, acc);
            acc = fmaf(aInv[i4*4+2], pv.z, acc);
            acc = fmaf(aInv[i4*4+3], pv.w, acc);
        }
        sPartV[q * (40 * 64) + t * 64 + n] = acc;
    }
    __syncthreads();
    for (int o = tid; o < nsteps * 64; o += 256) {
        sV[o] = sPartV[o] + sPartV[2560 + o] + sPartV[5120 + o] + sPartV[7680 + o];
    }
    __syncthreads();

    for (int j = 0; j < nsteps; ++j) {
        const float dj = sDelta[j];
        float h[16], v[16];
        #pragma unroll
        for (int i4 = 0; i4 < 4; ++i4) {
            float4 hv = *(const float4*)&sH[mb + i4 * 4];
            h[i4*4+0] = hv.x; h[i4*4+1] = hv.y; h[i4*4+2] = hv.z; h[i4*4+3] = hv.w;
            float4 vv = *(const float4*)&sV[j * 64 + mb + i4 * 4];
            v[i4*4+0] = vv.x; v[i4*4+1] = vv.y; v[i4*4+2] = vv.z; v[i4*4+3] = vv.w;
        }
        float acc = 0.0f;
        #pragma unroll
        for (int i = 0; i < 16; ++i) {
            acc = fmaf(h[i], fast_exp2(dj * aCol[i]), acc);
            acc = fmaf(fast_exp2(dj * aRow[i]), v[i], acc);
        }
        sPart[q * 64 + n] = acc;
        __syncthreads();
        if (tid < 64) {
            float hn = sPart[tid] + sPart[64 + tid] + sPart[128 + tid] + sPart[192 + tid]
                       - sV[j * 64 + tid];
            sH[tid] = hn;
            if (j >= warm) g_hs[(t0g + j) * 64 + tid] = hn;
        }
        __syncthreads();
    }
}

// ===========================================================================
// kernel_y2: Y += hs @ C_w^T.  M=4096, N=512, K=64.
// ===========================================================================
__global__ void kernel_y2(const float* __restrict__ Cw, float* __restrict__ Y) {
    __shared__ float As[2][16][132];
    __shared__ float Bs[2][16][132];
    const int tid = threadIdx.x;
    const int m0 = blockIdx.y * 128;
    const int n0 = blockIdx.x * 128;

    const int r0 = tid >> 2;
    const int r1 = 64 + r0;
    const int kq = (tid & 3) * 4;

    const int w = tid >> 5, lane = tid & 31;
    const int wm = w & 3, wn = w >> 2;
    const int r = lane >> 3, c = lane & 7;
    const int aoff = wm * 32 + r * 8;
    const int boff0 = wn * 64 + c * 4;
    const int boff1 = boff0 + 32;

    float acc[8][8] = {};
    float4 pa0, pa1, pb0, pb1;

    auto fetch = [&](int kt) {
        int kk = kt * 16;
        pa0 = *(const float4*)(g_hs + (m0 + r0) * 64 + kk + kq);
        pa1 = *(const float4*)(g_hs + (m0 + r1) * 64 + kk + kq);
        pb0 = *(const float4*)(Cw + (n0 + r0) * 64 + kk + kq);
        pb1 = *(const float4*)(Cw + (n0 + r1) * 64 + kk + kq);
    };
    auto stash = [&](int b) {
        As[b][kq+0][r0] = pa0.x; As[b][kq+1][r0] = pa0.y;
        As[b][kq+2][r0] = pa0.z; As[b][kq+3][r0] = pa0.w;
        As[b][kq+0][r1] = pa1.x; As[b][kq+1][r1] = pa1.y;
        As[b][kq+2][r1] = pa1.z; As[b][kq+3][r1] = pa1.w;
        Bs[b][kq+0][r0] = pb0.x; Bs[b][kq+1][r0] = pb0.y;
        Bs[b][kq+2][r0] = pb0.z; Bs[b][kq+3][r0] = pb0.w;
        Bs[b][kq+0][r1] = pb1.x; Bs[b][kq+1][r1] = pb1.y;
        Bs[b][kq+2][r1] = pb1.z; Bs[b][kq+3][r1] = pb1.w;
    };

    fetch(0);
    stash(0);
    __syncthreads();

    int buf = 0;
    for (int kt = 0; kt < 4; ++kt) {
        if (kt + 1 < 4) fetch(kt + 1);
        #pragma unroll
        for (int k = 0; k < 16; ++k) {
            float4 a0 = *(const float4*)&As[buf][k][aoff];
            float4 a1 = *(const float4*)&As[buf][k][aoff + 4];
            float4 b0 = *(const float4*)&Bs[buf][k][boff0];
            float4 b1 = *(const float4*)&Bs[buf][k][boff1];
            float av[8] = {a0.x, a0.y, a0.z, a0.w, a1.x, a1.y, a1.z, a1.w};
            float bv[8] = {b0.x, b0.y, b0.z, b0.w, b1.x, b1.y, b1.z, b1.w};
            #pragma unroll
            for (int i = 0; i < 8; ++i) {
                #pragma unroll
                for (int jj = 0; jj < 8; ++jj) {
                    acc[i][jj] = fmaf(av[i], bv[jj], acc[i][jj]);
                }
            }
        }
        if (kt + 1 < 4) {
            stash(buf ^ 1);
            __syncthreads();
            buf ^= 1;
        }
    }

    const int cg0 = n0 + boff0;
    const int cg1 = n0 + boff1;
    #pragma unroll
    for (int i = 0; i < 8; ++i) {
        int gm = m0 + aoff + i;
        float4 y0 = *(const float4*)(Y + gm * 512 + cg0);
        float4 y1 = *(const float4*)(Y + gm * 512 + cg1);
        y0.x += acc[i][0]; y0.y += acc[i][1]; y0.z += acc[i][2]; y0.w += acc[i][3];
        y1.x += acc[i][4]; y1.y += acc[i][5]; y1.z += acc[i][6]; y1.w += acc[i][7];
        *(float4*)(Y + gm * 512 + cg0) = y0;
        *(float4*)(Y + gm * 512 + cg1) = y1;
    }
}

// ===========================================================================
struct LaunchCtx {
    cudaStream_t s1, s2;
    cudaEvent_t e_root, e_prep, e_y1;
    LaunchCtx() {
        cudaStreamCreateWithFlags(&s1, cudaStreamNonBlocking);
        cudaStreamCreateWithFlags(&s2, cudaStreamNonBlocking);
        cudaEventCreateWithFlags(&e_root, cudaEventDisableTiming);
        cudaEventCreateWithFlags(&e_prep, cudaEventDisableTiming);
        cudaEventCreateWithFlags(&e_y1, cudaEventDisableTiming);
    }
};

extern "C" void kernel_launch(void* const* d_in, const int* in_sizes, int n_in,
                              void* d_out, int out_size) {
    const float* x   = (const float*)d_in[0];   // (B,S,H)
    const float* dlt = (const float*)d_in[1];   // (B,S)
    const float* A   = (const float*)d_in[2];   // (N,N)
    const float* Bw  = (const float*)d_in[3];   // (N,H)
    const float* Cw  = (const float*)d_in[4];   // (H,N)
    const float* Cb  = (const float*)d_in[5];   // (H)
    const float* Dw  = (const float*)d_in[6];   // (H,H)
    const float* Db  = (const float*)d_in[7];   // (H)
    float* Y = (float*)d_out;

    static LaunchCtx ctx;

    const int prep_smem = PREP_SMEM_FLOATS * 4;
    const int scan_smem = SCAN_SMEM_FLOATS * 4;
    cudaFuncSetAttribute(kernel_prep, cudaFuncAttributeMaxDynamicSharedMemorySize, prep_smem);
    cudaFuncSetAttribute(kernel_scan, cudaFuncAttributeMaxDynamicSharedMemorySize, scan_smem);
    cudaFuncSetAttribute(kernel_y1_mma, cudaFuncAttributeMaxDynamicSharedMemorySize, Y1_SMEM_BYTES);

    // Fork: s1 (prep), s2 (conv + y1) branch off the main stream.
    cudaEventRecord(ctx.e_root, 0);
    cudaStreamWaitEvent(ctx.s1, ctx.e_root, 0);
    cudaStreamWaitEvent(ctx.s2, ctx.e_root, 0);

    kernel_conv_x<<<TTOT * HDIM / 1024, 256, 0, ctx.s2>>>(x);
    kernel_conv_w<<<HDIM * HDIM / 1024, 256, 0, ctx.s2>>>(Dw);
    kernel_y1_mma<<<dim3(4, 32), 256, Y1_SMEM_BYTES, ctx.s2>>>(Cb, Db, Y);
    cudaEventRecord(ctx.e_y1, ctx.s2);

    kernel_prep<<<1, 512, prep_smem, ctx.s1>>>(A);
    cudaEventRecord(ctx.e_prep, ctx.s1);

    kernel_p<<<128, 256>>>(x, Bw);                 // main stream
    cudaStreamWaitEvent(0, ctx.e_prep, 0);         // scan needs Ainv + p
    kernel_scan<<<128, 256, scan_smem>>>(A, dlt);
    cudaStreamWaitEvent(0, ctx.e_y1, 0);           // y2 accumulates into Y
    kernel_y2<<<dim3(4, 32), 256>>>(Cw, Y);
}

// round 9
// speedup vs baseline: 2.3443x; 1.1362x over previous
#include <cuda_runtime.h>
#include <cuda_bf16.h>
#include <cstdint>

// Problem dims
#define BSZ 2
#define SLEN 2048
#define HDIM 512
#define NDIM 64
#define TTOT 4096   // BSZ*SLEN

// ---------------- scratch (device globals; no allocation allowed) ----------
__device__ __align__(16) float g_Ainv[NDIM * NDIM];
__device__ __align__(16) float g_p[TTOT * NDIM];      // p = x @ B_w^T
__device__ __align__(16) float g_hs[TTOT * NDIM];     // scan states
__device__ __align__(16) __nv_bfloat16 g_xh[TTOT * HDIM];   // x hi split
__device__ __align__(16) __nv_bfloat16 g_xl[TTOT * HDIM];   // x lo split
__device__ __align__(16) __nv_bfloat16 g_wh[HDIM * HDIM];   // Dw hi split
__device__ __align__(16) __nv_bfloat16 g_wl[HDIM * HDIM];   // Dw lo split

__device__ __forceinline__ float fast_exp2(float x) {
    float y;
    asm("ex2.approx.ftz.f32 %0, %1;" : "=f"(y) : "f"(x));
    return y;
}

__device__ __forceinline__ uint32_t smem_u32(const void* p) {
    return (uint32_t)__cvta_generic_to_shared(p);
}

__device__ __forceinline__ void ldsm4(uint32_t* r, uint32_t a) {
    asm volatile("ldmatrix.sync.aligned.m8n8.x4.shared.b16 {%0,%1,%2,%3}, [%4];"
                 : "=r"(r[0]), "=r"(r[1]), "=r"(r[2]), "=r"(r[3]) : "r"(a));
}
__device__ __forceinline__ void ldsm2(uint32_t* r, uint32_t a) {
    asm volatile("ldmatrix.sync.aligned.m8n8.x2.shared.b16 {%0,%1}, [%2];"
                 : "=r"(r[0]), "=r"(r[1]) : "r"(a));
}
__device__ __forceinline__ void mma16816(float* d, const uint32_t* a, const uint32_t* b) {
    asm volatile(
        "mma.sync.aligned.m16n8k16.row.col.f32.bf16.bf16.f32 "
        "{%0,%1,%2,%3}, {%4,%5,%6,%7}, {%8,%9}, {%0,%1,%2,%3};"
        : "+f"(d[0]), "+f"(d[1]), "+f"(d[2]), "+f"(d[3])
        : "r"(a[0]), "r"(a[1]), "r"(a[2]), "r"(a[3]), "r"(b[0]), "r"(b[1]));
}

// ===========================================================================
// kernel_conv_x / kernel_conv_w: fp32 -> (hi, lo) bf16 splits.
// ===========================================================================
__global__ void kernel_conv_x(const float* __restrict__ x) {
    int i = (blockIdx.x * 256 + threadIdx.x) * 4;
    float4 v = *(const float4*)(x + i);
    __nv_bfloat16 h0 = __float2bfloat16(v.x);
    __nv_bfloat16 h1 = __float2bfloat16(v.y);
    __nv_bfloat16 h2 = __float2bfloat16(v.z);
    __nv_bfloat16 h3 = __float2bfloat16(v.w);
    __nv_bfloat16 l0 = __float2bfloat16(v.x - __bfloat162float(h0));
    __nv_bfloat16 l1 = __float2bfloat16(v.y - __bfloat162float(h1));
    __nv_bfloat16 l2 = __float2bfloat16(v.z - __bfloat162float(h2));
    __nv_bfloat16 l3 = __float2bfloat16(v.w - __bfloat162float(h3));
    *(__nv_bfloat162*)&g_xh[i + 0] = __halves2bfloat162(h0, h1);
    *(__nv_bfloat162*)&g_xh[i + 2] = __halves2bfloat162(h2, h3);
    *(__nv_bfloat162*)&g_xl[i + 0] = __halves2bfloat162(l0, l1);
    *(__nv_bfloat162*)&g_xl[i + 2] = __halves2bfloat162(l2, l3);
}
__global__ void kernel_conv_w(const float* __restrict__ w) {
    int i = (blockIdx.x * 256 + threadIdx.x) * 4;
    float4 v = *(const float4*)(w + i);
    __nv_bfloat16 h0 = __float2bfloat16(v.x);
    __nv_bfloat16 h1 = __float2bfloat16(v.y);
    __nv_bfloat16 h2 = __float2bfloat16(v.z);
    __nv_bfloat16 h3 = __float2bfloat16(v.w);
    __nv_bfloat16 l0 = __float2bfloat16(v.x - __bfloat162float(h0));
    __nv_bfloat16 l1 = __float2bfloat16(v.y - __bfloat162float(h1));
    __nv_bfloat16 l2 = __float2bfloat16(v.z - __bfloat162float(h2));
    __nv_bfloat16 l3 = __float2bfloat16(v.w - __bfloat162float(h3));
    *(__nv_bfloat162*)&g_wh[i + 0] = __halves2bfloat162(h0, h1);
    *(__nv_bfloat162*)&g_wh[i + 2] = __halves2bfloat162(h2, h3);
    *(__nv_bfloat162*)&g_wl[i + 0] = __halves2bfloat162(l0, l1);
    *(__nv_bfloat162*)&g_wl[i + 2] = __halves2bfloat162(l2, l3);
}

// ===========================================================================
// kernel_y1_mma: Y = x @ Dw^T + (Cb+Db), bf16 tensor-core 2-way split.
// ===========================================================================
#define Y1_TS (128 * 40)
#define Y1_SMEM_BYTES (8 * Y1_TS * 2)

__global__ __launch_bounds__(256, 1)
void kernel_y1_mma(const float* __restrict__ Cb, const float* __restrict__ Db,
                   float* __restrict__ Y) {
    extern __shared__ __nv_bfloat16 smem[];
    __nv_bfloat16* sAh = smem;
    __nv_bfloat16* sAl = smem + 2 * Y1_TS;
    __nv_bfloat16* sBh = smem + 4 * Y1_TS;
    __nv_bfloat16* sBl = smem + 6 * Y1_TS;

    const int tid = threadIdx.x;
    const int m0 = blockIdx.y * 128;
    const int n0 = blockIdx.x * 128;

    const int lrow = tid >> 2;
    const int lch  = (tid & 3) * 8;

    const int lane = tid & 31;
    const int w = tid >> 5;
    const int wm = w & 1;
    const int wn = w >> 1;
    const int a_row = wm * 64 + (lane & 15);
    const int a_col = (lane >> 4) * 8;
    const int b_row = wn * 32 + (lane & 7);
    const int b_col = ((lane >> 3) & 1) * 8;

    float acc[4][4][4] = {};

    uint4 pAh0, pAh1, pAl0, pAl1, pBh0, pBh1, pBl0, pBl1;
    auto fetch = [&](int kt) {
        const int kk = kt * 32 + lch;
        pAh0 = *(const uint4*)&g_xh[(m0 + lrow) * 512 + kk];
        pAh1 = *(const uint4*)&g_xh[(m0 + lrow + 64) * 512 + kk];
        pAl0 = *(const uint4*)&g_xl[(m0 + lrow) * 512 + kk];
        pAl1 = *(const uint4*)&g_xl[(m0 + lrow + 64) * 512 + kk];
        pBh0 = *(const uint4*)&g_wh[(n0 + lrow) * 512 + kk];
        pBh1 = *(const uint4*)&g_wh[(n0 + lrow + 64) * 512 + kk];
        pBl0 = *(const uint4*)&g_wl[(n0 + lrow) * 512 + kk];
        pBl1 = *(const uint4*)&g_wl[(n0 + lrow + 64) * 512 + kk];
    };
    auto stash = [&](int b) {
        const int o0 = b * Y1_TS + lrow * 40 + lch;
        const int o1 = b * Y1_TS + (lrow + 64) * 40 + lch;
        *(uint4*)&sAh[o0] = pAh0;  *(uint4*)&sAh[o1] = pAh1;
        *(uint4*)&sAl[o0] = pAl0;  *(uint4*)&sAl[o1] = pAl1;
        *(uint4*)&sBh[o0] = pBh0;  *(uint4*)&sBh[o1] = pBh1;
        *(uint4*)&sBl[o0] = pBl0;  *(uint4*)&sBl[o1] = pBl1;
    };

    fetch(0);
    stash(0);
    __syncthreads();

    int buf = 0;
    for (int kt = 0; kt < 16; ++kt) {
        if (kt + 1 < 16) fetch(kt + 1);
        const __nv_bfloat16* bAh = sAh + buf * Y1_TS;
        const __nv_bfloat16* bAl = sAl + buf * Y1_TS;
        const __nv_bfloat16* bBh = sBh + buf * Y1_TS;
        const __nv_bfloat16* bBl = sBl + buf * Y1_TS;
        #pragma unroll
        for (int k16 = 0; k16 < 2; ++k16) {
            uint32_t ah[4][4], al[4][4], bh[4][2], bl[4][2];
            #pragma unroll
            for (int mi = 0; mi < 4; ++mi) {
                ldsm4(ah[mi], smem_u32(bAh + (a_row + mi * 16) * 40 + a_col + k16 * 16));
                ldsm4(al[mi], smem_u32(bAl + (a_row + mi * 16) * 40 + a_col + k16 * 16));
            }
            #pragma unroll
            for (int ni = 0; ni < 4; ++ni) {
                ldsm2(bh[ni], smem_u32(bBh + (b_row + ni * 8) * 40 + b_col + k16 * 16));
                ldsm2(bl[ni], smem_u32(bBl + (b_row + ni * 8) * 40 + b_col + k16 * 16));
            }
            #pragma unroll
            for (int mi = 0; mi < 4; ++mi) {
                #pragma unroll
                for (int ni = 0; ni < 4; ++ni) {
                    mma16816(acc[mi][ni], ah[mi], bh[ni]);
                    mma16816(acc[mi][ni], ah[mi], bl[ni]);
                    mma16816(acc[mi][ni], al[mi], bh[ni]);
                }
            }
        }
        if (kt + 1 < 16) {
            stash(buf ^ 1);
            __syncthreads();
            buf ^= 1;
        }
    }

    #pragma unroll
    for (int ni = 0; ni < 4; ++ni) {
        const int gn = n0 + wn * 32 + ni * 8 + (lane & 3) * 2;
        float2 cb = *(const float2*)(Cb + gn);
        float2 db = *(const float2*)(Db + gn);
        const float bx = cb.x + db.x, by = cb.y + db.y;
        #pragma unroll
        for (int mi = 0; mi < 4; ++mi) {
            const int gm = m0 + wm * 64 + mi * 16 + (lane >> 2);
            float2 o0 = {acc[mi][ni][0] + bx, acc[mi][ni][1] + by};
            float2 o1 = {acc[mi][ni][2] + bx, acc[mi][ni][3] + by};
            *(float2*)(Y + gm * 512 + gn) = o0;
            *(float2*)(Y + (gm + 8) * 512 + gn) = o1;
        }
    }
}

// ===========================================================================
// kernel_prep: NO-PIVOT Gauss-Jordan, 1 barrier/iter.
// FIX vs failed round: the pivot reciprocal is captured AT ITERATION k
// (sDiagRcp[k]), because later iterations corrupt the left-half factor
// columns (incl. the diagonal) via stale entries. The RIGHT half is clean:
// its columns are updated every iteration with clean multipliers, so
// A^-1 = diag(sDiagRcp) * right-half. Then TWO Newton steps X<-X(2I-AX)
// square away any no-pivot growth. 512 threads.
// ===========================================================================
#define PREP_SMEM_FLOATS (64*132 + 64*68 + 64*68)

__global__ void kernel_prep(const float* __restrict__ A) {
    extern __shared__ float sm[];
    float* M = sm;                 // 64 x 132 augmented [A|I]
    float* X = M + 64 * 132;       // 64 x 68
    float* T = X + 64 * 68;        // 64 x 68
    __shared__ float sDiagRcp[64];
    const int tid = threadIdx.x;

    for (int e = tid; e < 4096; e += 512) {
        int i = e >> 6, j = e & 63;
        M[i * 132 + j] = A[e];
        M[i * 132 + 64 + j] = (i == j) ? 1.0f : 0.0f;
    }
    __syncthreads();

    const int cg = tid & 31;        // 4-col group over 128 cols
    const int rbase = tid >> 5;     // 0..15; rows rbase + 16*s

    for (int k = 0; k < 64; ++k) {
        // every thread: broadcast-read pivot, local reciprocal (no sync needed)
        const float rcp = 1.0f / M[k * 132 + k];     // clean at iteration k
        if (tid == 0) sDiagRcp[k] = rcp;
        float4 fk = *(const float4*)&M[k * 132 + cg * 4];
        const int kin = k - cg * 4;            // 0..3 if col k in this group
        #pragma unroll
        for (int s = 0; s < 4; ++s) {
            int i = rbase + 16 * s;
            if (i == k) continue;
            float f = M[i * 132 + k] * rcp;
            float4 vv = *(const float4*)&M[i * 132 + cg * 4];
            float4 nv;
            nv.x = fmaf(-f, fk.x, vv.x);
            nv.y = fmaf(-f, fk.y, vv.y);
            nv.z = fmaf(-f, fk.z, vv.z);
            nv.w = fmaf(-f, fk.w, vv.w);
            if (kin == 0) nv.x = vv.x;         // preserve factor column k this iter
            else if (kin == 1) nv.y = vv.y;
            else if (kin == 2) nv.z = vv.z;
            else if (kin == 3) nv.w = vv.w;
            *(float4*)&M[i * 132 + cg * 4] = nv;
        }
        __syncthreads();
    }

    // X = diag(sDiagRcp) * right half (right half is clean; diagonal is NOT)
    for (int e = tid; e < 4096; e += 512) {
        int i = e >> 6, j = e & 63;
        X[i * 68 + j] = M[i * 132 + 64 + j] * sDiagRcp[i];
    }
    __syncthreads();
    // reload A into left half
    for (int e = tid; e < 4096; e += 512) {
        int i = e >> 6, j = e & 63;
        M[i * 132 + j] = A[e];
    }
    __syncthreads();

    // two Newton steps: X <- X (2I - A X)
    for (int it = 0; it < 2; ++it) {
        for (int o = tid; o < 1024; o += 512) {
            int i = o >> 4, j4 = (o & 15) * 4;
            float4 acc;
            acc.x = (i == j4 + 0) ? 2.0f : 0.0f;
            acc.y = (i == j4 + 1) ? 2.0f : 0.0f;
            acc.z = (i == j4 + 2) ? 2.0f : 0.0f;
            acc.w = (i == j4 + 3) ? 2.0f : 0.0f;
            #pragma unroll 8
            for (int k2 = 0; k2 < 64; ++k2) {
                float a = M[i * 132 + k2];
                float4 xv = *(const float4*)&X[k2 * 68 + j4];
                acc.x = fmaf(-a, xv.x, acc.x);
                acc.y = fmaf(-a, xv.y, acc.y);
                acc.z = fmaf(-a, xv.z, acc.z);
                acc.w = fmaf(-a, xv.w, acc.w);
            }
            *(float4*)&T[i * 68 + j4] = acc;
        }
        __syncthreads();
        float4 r[2];
        #pragma unroll
        for (int t2 = 0; t2 < 2; ++t2) {
            int o = tid + t2 * 512;
            int i = o >> 4, j4 = (o & 15) * 4;
            float4 acc = {0.f, 0.f, 0.f, 0.f};
            #pragma unroll 8
            for (int k2 = 0; k2 < 64; ++k2) {
                float a = X[i * 68 + k2];
                float4 tv = *(const float4*)&T[k2 * 68 + j4];
                acc.x = fmaf(a, tv.x, acc.x);
                acc.y = fmaf(a, tv.y, acc.y);
                acc.z = fmaf(a, tv.z, acc.z);
                acc.w = fmaf(a, tv.w, acc.w);
            }
            r[t2] = acc;
        }
        __syncthreads();
        #pragma unroll
        for (int t2 = 0; t2 < 2; ++t2) {
            int o = tid + t2 * 512;
            int i = o >> 4, j4 = (o & 15) * 4;
            *(float4*)&X[i * 68 + j4] = r[t2];
        }
        __syncthreads();
    }

    for (int o = tid; o < 1024; o += 512) {
        int i = o >> 4, j4 = (o & 15) * 4;
        *(float4*)&g_Ainv[i * 64 + j4] = *(const float4*)&X[i * 68 + j4];
    }
}

// ===========================================================================
// kernel_p: p = x @ B_w^T   (4096 x 64, K=512), NT GEMM.
// ===========================================================================
__global__ void kernel_p(const float* __restrict__ Xin, const float* __restrict__ Bw) {
    __shared__ float As[2][32][36];
    __shared__ float Bs[2][32][68];
    const int tid = threadIdx.x;
    const int m0 = blockIdx.x * 32;
    const int tx = tid & 15, ty = tid >> 4;

    const int ar  = tid >> 3;
    const int akq = (tid & 7) * 4;
    const int br0 = ar;
    const int br1 = 32 + ar;

    float acc[2][4] = {};
    float4 pa, pb0, pb1;

    pa  = *(const float4*)(Xin + (m0 + ar) * 512 + akq);
    pb0 = *(const float4*)(Bw + br0 * 512 + akq);
    pb1 = *(const float4*)(Bw + br1 * 512 + akq);
    As[0][akq+0][ar] = pa.x;  As[0][akq+1][ar] = pa.y;
    As[0][akq+2][ar] = pa.z;  As[0][akq+3][ar] = pa.w;
    Bs[0][akq+0][br0] = pb0.x; Bs[0][akq+1][br0] = pb0.y;
    Bs[0][akq+2][br0] = pb0.z; Bs[0][akq+3][br0] = pb0.w;
    Bs[0][akq+0][br1] = pb1.x; Bs[0][akq+1][br1] = pb1.y;
    Bs[0][akq+2][br1] = pb1.z; Bs[0][akq+3][br1] = pb1.w;
    __syncthreads();

    int buf = 0;
    for (int kt = 0; kt < 16; ++kt) {
        if (kt + 1 < 16) {
            int kk = (kt + 1) * 32;
            pa  = *(const float4*)(Xin + (m0 + ar) * 512 + kk + akq);
            pb0 = *(const float4*)(Bw + br0 * 512 + kk + akq);
            pb1 = *(const float4*)(Bw + br1 * 512 + kk + akq);
        }
        #pragma unroll
        for (int k = 0; k < 32; ++k) {
            float a0 = As[buf][k][ty * 2 + 0];
            float a1 = As[buf][k][ty * 2 + 1];
            float4 bv = *(const float4*)&Bs[buf][k][tx * 4];
            acc[0][0] = fmaf(a0, bv.x, acc[0][0]);
            acc[0][1] = fmaf(a0, bv.y, acc[0][1]);
            acc[0][2] = fmaf(a0, bv.z, acc[0][2]);
            acc[0][3] = fmaf(a0, bv.w, acc[0][3]);
            acc[1][0] = fmaf(a1, bv.x, acc[1][0]);
            acc[1][1] = fmaf(a1, bv.y, acc[1][1]);
            acc[1][2] = fmaf(a1, bv.z, acc[1][2]);
            acc[1][3] = fmaf(a1, bv.w, acc[1][3]);
        }
        if (kt + 1 < 16) {
            int nb = buf ^ 1;
            As[nb][akq+0][ar] = pa.x;  As[nb][akq+1][ar] = pa.y;
            As[nb][akq+2][ar] = pa.z;  As[nb][akq+3][ar] = pa.w;
            Bs[nb][akq+0][br0] = pb0.x; Bs[nb][akq+1][br0] = pb0.y;
            Bs[nb][akq+2][br0] = pb0.z; Bs[nb][akq+3][br0] = pb0.w;
            Bs[nb][akq+0][br1] = pb1.x; Bs[nb][akq+1][br1] = pb1.y;
            Bs[nb][akq+2][br1] = pb1.z; Bs[nb][akq+3][br1] = pb1.w;
            __syncthreads();
            buf = nb;
        }
    }

    #pragma unroll
    for (int i = 0; i < 2; ++i) {
        float4 o;
        o.x = acc[i][0]; o.y = acc[i][1]; o.z = acc[i][2]; o.w = acc[i][3];
        *(float4*)&g_p[(m0 + ty * 2 + i) * 64 + tx * 4] = o;
    }
}

// ===========================================================================
// kernel_scan: chunked selective scan, register-resident A slices.
// 256 blocks = chunks of 16 steps + 4-step warmup (truncation <= 2e-7).
// ===========================================================================
#define SCAN_STEPS_MAX 20
#define SCAN_SMEM_FLOATS (SCAN_STEPS_MAX*64 + SCAN_STEPS_MAX*64 + 4*SCAN_STEPS_MAX*64 + 64 + 256 + 64)

__global__ void kernel_scan(const float* __restrict__ A, const float* __restrict__ dlt) {
    extern __shared__ float sm[];
    float* sP     = sm;
    float* sV     = sP + SCAN_STEPS_MAX * 64;
    float* sPartV = sV + SCAN_STEPS_MAX * 64;
    float* sDelta = sPartV + 4 * SCAN_STEPS_MAX * 64;
    float* sPart  = sDelta + 64;
    float* sH     = sPart + 256;

    const int tid = threadIdx.x;
    const int g = blockIdx.x;                            // 0..255
    const int lc = g & 127;
    const int warm = lc ? 4 : 0;
    const int t0g = g * 16 - warm;
    const int nsteps = 16 + warm;

    const float LOG2E = 1.4426950408889634f;
    const int n = tid & 63, q = tid >> 6;
    const int mb = q * 16;

    float aCol[16], aRow[16], aInv[16];
    #pragma unroll
    for (int i = 0; i < 16; ++i) {
        aCol[i] = LOG2E * A[(mb + i) * 64 + n];
    }
    #pragma unroll
    for (int i4 = 0; i4 < 4; ++i4) {
        float4 r = *(const float4*)(A + n * 64 + mb + i4 * 4);
        aRow[i4*4+0] = LOG2E * r.x; aRow[i4*4+1] = LOG2E * r.y;
        aRow[i4*4+2] = LOG2E * r.z; aRow[i4*4+3] = LOG2E * r.w;
        float4 iv = *(const float4*)(g_Ainv + n * 64 + mb + i4 * 4);
        aInv[i4*4+0] = iv.x; aInv[i4*4+1] = iv.y;
        aInv[i4*4+2] = iv.z; aInv[i4*4+3] = iv.w;
    }

    for (int e = tid; e < nsteps * 64; e += 256) {
        sP[e] = g_p[t0g * 64 + e];
    }
    if (tid < nsteps) sDelta[tid] = dlt[t0g + tid];
    if (tid < 64) sH[tid] = 0.0f;
    __syncthreads();

    for (int t = 0; t < nsteps; ++t) {
        float acc = 0.0f;
        #pragma unroll
        for (int i4 = 0; i4 < 4; ++i4) {
            float4 pv = *(const float4*)&sP[t * 64 + mb + i4 * 4];
            acc = fmaf(aInv[i4*4+0], pv.x, acc);
            acc = fmaf(aInv[i4*4+1], pv.y, acc);
            acc = fmaf(aInv[i4*4+2], pv.z, acc);
            acc = fmaf(aInv[i4*4+3], pv.w, acc);
        }
        sPartV[q * (SCAN_STEPS_MAX * 64) + t * 64 + n] = acc;
    }
    __syncthreads();
    for (int o = tid; o < nsteps * 64; o += 256) {
        sV[o] = sPartV[o] + sPartV[SCAN_STEPS_MAX*64 + o]
              + sPartV[2*SCAN_STEPS_MAX*64 + o] + sPartV[3*SCAN_STEPS_MAX*64 + o];
    }
    __syncthreads();

    for (int j = 0; j < nsteps; ++j) {
        const float dj = sDelta[j];
        float h[16], v[16];
        #pragma unroll
        for (int i4 = 0; i4 < 4; ++i4) {
            float4 hv = *(const float4*)&sH[mb + i4 * 4];
            h[i4*4+0] = hv.x; h[i4*4+1] = hv.y; h[i4*4+2] = hv.z; h[i4*4+3] = hv.w;
            float4 vv = *(const float4*)&sV[j * 64 + mb + i4 * 4];
            v[i4*4+0] = vv.x; v[i4*4+1] = vv.y; v[i4*4+2] = vv.z; v[i4*4+3] = vv.w;
        }
        float acc = 0.0f;
        #pragma unroll
        for (int i = 0; i < 16; ++i) {
            acc = fmaf(h[i], fast_exp2(dj * aCol[i]), acc);
            acc = fmaf(fast_exp2(dj * aRow[i]), v[i], acc);
        }
        sPart[q * 64 + n] = acc;
        __syncthreads();
        if (tid < 64) {
            float hn = sPart[tid] + sPart[64 + tid] + sPart[128 + tid] + sPart[192 + tid]
                       - sV[j * 64 + tid];
            sH[tid] = hn;
            if (j >= warm) g_hs[(t0g + j) * 64 + tid] = hn;
        }
        __syncthreads();
    }
}

// ===========================================================================
// kernel_y2: Y += hs @ C_w^T.  M=4096, N=512, K=64.
// ===========================================================================
__global__ void kernel_y2(const float* __restrict__ Cw, float* __restrict__ Y) {
    __shared__ float As[2][16][132];
    __shared__ float Bs[2][16][132];
    const int tid = threadIdx.x;
    const int m0 = blockIdx.y * 128;
    const int n0 = blockIdx.x * 128;

    const int r0 = tid >> 2;
    const int r1 = 64 + r0;
    const int kq = (tid & 3) * 4;

    const int w = tid >> 5, lane = tid & 31;
    const int wm = w & 3, wn = w >> 2;
    const int r = lane >> 3, c = lane & 7;
    const int aoff = wm * 32 + r * 8;
    const int boff0 = wn * 64 + c * 4;
    const int boff1 = boff0 + 32;

    float acc[8][8] = {};
    float4 pa0, pa1, pb0, pb1;

    auto fetch = [&](int kt) {
        int kk = kt * 16;
        pa0 = *(const float4*)(g_hs + (m0 + r0) * 64 + kk + kq);
        pa1 = *(const float4*)(g_hs + (m0 + r1) * 64 + kk + kq);
        pb0 = *(const float4*)(Cw + (n0 + r0) * 64 + kk + kq);
        pb1 = *(const float4*)(Cw + (n0 + r1) * 64 + kk + kq);
    };
    auto stash = [&](int b) {
        As[b][kq+0][r0] = pa0.x; As[b][kq+1][r0] = pa0.y;
        As[b][kq+2][r0] = pa0.z; As[b][kq+3][r0] = pa0.w;
        As[b][kq+0][r1] = pa1.x; As[b][kq+1][r1] = pa1.y;
        As[b][kq+2][r1] = pa1.z; As[b][kq+3][r1] = pa1.w;
        Bs[b][kq+0][r0] = pb0.x; Bs[b][kq+1][r0] = pb0.y;
        Bs[b][kq+2][r0] = pb0.z; Bs[b][kq+3][r0] = pb0.w;
        Bs[b][kq+0][r1] = pb1.x; Bs[b][kq+1][r1] = pb1.y;
        Bs[b][kq+2][r1] = pb1.z; Bs[b][kq+3][r1] = pb1.w;
    };

    fetch(0);
    stash(0);
    __syncthreads();

    int buf = 0;
    for (int kt = 0; kt < 4; ++kt) {
        if (kt + 1 < 4) fetch(kt + 1);
        #pragma unroll
        for (int k = 0; k < 16; ++k) {
            float4 a0 = *(const float4*)&As[buf][k][aoff];
            float4 a1 = *(const float4*)&As[buf][k][aoff + 4];
            float4 b0 = *(const float4*)&Bs[buf][k][boff0];
            float4 b1 = *(const float4*)&Bs[buf][k][boff1];
            float av[8] = {a0.x, a0.y, a0.z, a0.w, a1.x, a1.y, a1.z, a1.w};
            float bv[8] = {b0.x, b0.y, b0.z, b0.w, b1.x, b1.y, b1.z, b1.w};
            #pragma unroll
            for (int i = 0; i < 8; ++i) {
                #pragma unroll
                for (int jj = 0; jj < 8; ++jj) {
                    acc[i][jj] = fmaf(av[i], bv[jj], acc[i][jj]);
                }
            }
        }
        if (kt + 1 < 4) {
            stash(buf ^ 1);
            __syncthreads();
            buf ^= 1;
        }
    }

    const int cg0 = n0 + boff0;
    const int cg1 = n0 + boff1;
    #pragma unroll
    for (int i = 0; i < 8; ++i) {
        int gm = m0 + aoff + i;
        float4 y0 = *(const float4*)(Y + gm * 512 + cg0);
        float4 y1 = *(const float4*)(Y + gm * 512 + cg1);
        y0.x += acc[i][0]; y0.y += acc[i][1]; y0.z += acc[i][2]; y0.w += acc[i][3];
        y1.x += acc[i][4]; y1.y += acc[i][5]; y1.z += acc[i][6]; y1.w += acc[i][7];
        *(float4*)(Y + gm * 512 + cg0) = y0;
        *(float4*)(Y + gm * 512 + cg1) = y1;
    }
}

// ===========================================================================
struct LaunchCtx {
    cudaStream_t s1, s2;
    cudaEvent_t e_root, e_prep, e_y1;
    LaunchCtx() {
        cudaStreamCreateWithFlags(&s1, cudaStreamNonBlocking);
        cudaStreamCreateWithFlags(&s2, cudaStreamNonBlocking);
        cudaEventCreateWithFlags(&e_root, cudaEventDisableTiming);
        cudaEventCreateWithFlags(&e_prep, cudaEventDisableTiming);
        cudaEventCreateWithFlags(&e_y1, cudaEventDisableTiming);
    }
};

extern "C" void kernel_launch(void* const* d_in, const int* in_sizes, int n_in,
                              void* d_out, int out_size) {
    const float* x   = (const float*)d_in[0];   // (B,S,H)
    const float* dlt = (const float*)d_in[1];   // (B,S)
    const float* A   = (const float*)d_in[2];   // (N,N)
    const float* Bw  = (const float*)d_in[3];   // (N,H)
    const float* Cw  = (const float*)d_in[4];   // (H,N)
    const float* Cb  = (const float*)d_in[5];   // (H)
    const float* Dw  = (const float*)d_in[6];   // (H,H)
    const float* Db  = (const float*)d_in[7];   // (H)
    float* Y = (float*)d_out;

    static LaunchCtx ctx;

    const int prep_smem = PREP_SMEM_FLOATS * 4;
    const int scan_smem = SCAN_SMEM_FLOATS * 4;
    cudaFuncSetAttribute(kernel_prep, cudaFuncAttributeMaxDynamicSharedMemorySize, prep_smem);
    cudaFuncSetAttribute(kernel_scan, cudaFuncAttributeMaxDynamicSharedMemorySize, scan_smem);
    cudaFuncSetAttribute(kernel_y1_mma, cudaFuncAttributeMaxDynamicSharedMemorySize, Y1_SMEM_BYTES);

    // Fork: s1 (prep), s2 (conv + y1) branch off the main stream.
    cudaEventRecord(ctx.e_root, 0);
    cudaStreamWaitEvent(ctx.s1, ctx.e_root, 0);
    cudaStreamWaitEvent(ctx.s2, ctx.e_root, 0);

    kernel_conv_x<<<TTOT * HDIM / 1024, 256, 0, ctx.s2>>>(x);
    kernel_conv_w<<<HDIM * HDIM / 1024, 256, 0, ctx.s2>>>(Dw);
    kernel_y1_mma<<<dim3(4, 32), 256, Y1_SMEM_BYTES, ctx.s2>>>(Cb, Db, Y);
    cudaEventRecord(ctx.e_y1, ctx.s2);

    kernel_prep<<<1, 512, prep_smem, ctx.s1>>>(A);
    cudaEventRecord(ctx.e_prep, ctx.s1);

    kernel_p<<<128, 256>>>(x, Bw);                 // main stream
    cudaStreamWaitEvent(0, ctx.e_prep, 0);         // scan needs Ainv + p
    kernel_scan<<<256, 256, scan_smem>>>(A, dlt);
    cudaStreamWaitEvent(0, ctx.e_y1, 0);           // y2 accumulates into Y
    kernel_y2<<<dim3(4, 32), 256>>>(Cw, Y);
}